// round 1
// baseline (speedup 1.0000x reference)
#include <cuda_runtime.h>
#include <math.h>

#define N_NODES 50000
#define N_EDGES 800000
#define N_GRAPHS 64
#define F_IN 128
#define H1 512
#define H2 256
#define H3 128
#define N_CLS 10
#define BN_EPS 1e-5f
#define HMAX 512

// ------------------------ scratch (device globals; no allocs) ------------------------
__device__ float  g_deg[N_NODES];                    // deg, then dinv (in place)
__device__ float  g_h  [(size_t)N_NODES * HMAX];     // h = A @ W
__device__ float  g_agg[(size_t)N_NODES * HMAX];     // aggregated messages
__device__ float  g_act[(size_t)N_NODES * HMAX];     // relu(bn(agg)) -> next layer input
__device__ double g_sum[HMAX];
__device__ double g_sumsq[HMAX];
__device__ float  g_scale[HMAX];
__device__ float  g_shift[HMAX];
__device__ float  g_pool[N_GRAPHS * H3];
__device__ float  g_cnt [N_GRAPHS];

// ------------------------ degree / dinv ------------------------
__global__ void init_deg_kernel() {
    int i = blockIdx.x * blockDim.x + threadIdx.x;
    if (i < N_NODES) g_deg[i] = 1.0f;  // self-loop
}

__global__ void count_deg_kernel(const int* __restrict__ ei) {
    int e = blockIdx.x * blockDim.x + threadIdx.x;
    if (e < N_EDGES) atomicAdd(&g_deg[ei[N_EDGES + e]], 1.0f);  // target = col
}

__global__ void finalize_dinv_kernel() {
    int i = blockIdx.x * blockDim.x + threadIdx.x;
    if (i < N_NODES) g_deg[i] = rsqrtf(g_deg[i]);
}

// ------------------------ GEMM: h = A@W ; agg = h * dinv^2 (self-loop) ------------------------
// BM=BN=64, BK=16, 256 threads, 4x4 per thread. N multiple of 64, K multiple of 16.
__global__ void gemm_selfloop_kernel(const float* __restrict__ A,
                                     const float* __restrict__ B,
                                     int M, int K, int N) {
    __shared__ float sA[16][65];   // [k][m], padded vs bank conflicts on store
    __shared__ float sB[16][64];   // [k][n]

    int t  = threadIdx.x;          // 0..255
    int tx = t & 15;               // n-dir
    int ty = t >> 4;               // m-dir
    int bm = blockIdx.y * 64;
    int bn = blockIdx.x * 64;

    float acc[4][4] = {};

    for (int k0 = 0; k0 < K; k0 += 16) {
        #pragma unroll
        for (int i = 0; i < 4; i++) {
            int idx = t + i * 256;          // 1024 elems: 64m x 16k
            int m   = idx >> 4;
            int kk  = idx & 15;
            int gm  = bm + m;
            sA[kk][m] = (gm < M) ? A[(size_t)gm * K + k0 + kk] : 0.0f;
        }
        #pragma unroll
        for (int i = 0; i < 4; i++) {
            int idx = t + i * 256;          // 1024 elems: 16k x 64n
            int n   = idx & 63;
            int kk  = idx >> 6;
            sB[kk][n] = B[(size_t)(k0 + kk) * N + bn + n];
        }
        __syncthreads();

        #pragma unroll
        for (int kk = 0; kk < 16; kk++) {
            float a[4], b[4];
            #pragma unroll
            for (int i = 0; i < 4; i++) a[i] = sA[kk][ty * 4 + i];
            #pragma unroll
            for (int j = 0; j < 4; j++) b[j] = sB[kk][tx * 4 + j];
            #pragma unroll
            for (int i = 0; i < 4; i++)
                #pragma unroll
                for (int j = 0; j < 4; j++)
                    acc[i][j] += a[i] * b[j];
        }
        __syncthreads();
    }

    #pragma unroll
    for (int i = 0; i < 4; i++) {
        int m = bm + ty * 4 + i;
        if (m >= M) continue;
        float di = g_deg[m];       // dinv
        float sl = di * di;        // self-loop norm
        #pragma unroll
        for (int j = 0; j < 4; j++) {
            int n = bn + tx * 4 + j;
            float v = acc[i][j];
            size_t o = (size_t)m * N + n;
            g_h[o]   = v;
            g_agg[o] = v * sl;
        }
    }
}

// ------------------------ edge scatter: agg[col] += h[row] * dinv[row]*dinv[col] ------------------------
// one thread per (edge, 4-feature group); fg = F/4 is a power of two
__global__ void scatter_edges_kernel(const int* __restrict__ ei, int F, int fg_log2, int total) {
    int idx = blockIdx.x * blockDim.x + threadIdx.x;
    if (idx >= total) return;
    int e = idx >> fg_log2;
    int j = idx & ((1 << fg_log2) - 1);
    int r = ei[e];
    int c = ei[N_EDGES + e];
    float norm = g_deg[r] * g_deg[c];
    float4 hv = *(const float4*)&g_h[(size_t)r * F + 4 * j];
    float* dst = &g_agg[(size_t)c * F + 4 * j];
    atomicAdd(dst + 0, hv.x * norm);
    atomicAdd(dst + 1, hv.y * norm);
    atomicAdd(dst + 2, hv.z * norm);
    atomicAdd(dst + 3, hv.w * norm);
}

// ------------------------ BatchNorm ------------------------
__global__ void zero_stats_kernel() {
    int f = threadIdx.x;
    g_sum[f] = 0.0;
    g_sumsq[f] = 0.0;
}

// blockDim = F; grid = 200 blocks of 250 rows (50000 = 200*250)
__global__ void bn_stats_kernel(int F) {
    int f  = threadIdx.x;
    int r0 = blockIdx.x * 250;
    double s = 0.0, s2 = 0.0;
    for (int r = r0; r < r0 + 250; r++) {
        float v = g_agg[(size_t)r * F + f];
        s  += (double)v;
        s2 += (double)v * (double)v;
    }
    atomicAdd(&g_sum[f], s);
    atomicAdd(&g_sumsq[f], s2);
}

__global__ void bn_finalize_kernel(const float* __restrict__ gamma,
                                   const float* __restrict__ beta) {
    int f = threadIdx.x;
    double mean = g_sum[f] * (1.0 / N_NODES);
    double var  = g_sumsq[f] * (1.0 / N_NODES) - mean * mean;
    float scale = gamma[f] * rsqrtf((float)var + BN_EPS);
    g_scale[f] = scale;
    g_shift[f] = beta[f] - (float)mean * scale;
}

__global__ void bn_apply_relu_kernel(int mask, int total) {
    int idx = blockIdx.x * blockDim.x + threadIdx.x;
    if (idx >= total) return;
    int f = idx & mask;
    g_act[idx] = fmaxf(g_agg[idx] * g_scale[f] + g_shift[f], 0.0f);
}

// ------------------------ global mean pool + output linear ------------------------
__global__ void zero_pool_kernel() {
    int i = blockIdx.x * blockDim.x + threadIdx.x;
    if (i < N_GRAPHS * H3) g_pool[i] = 0.0f;
    if (i < N_GRAPHS) g_cnt[i] = 0.0f;
}

__global__ void pool_accum_kernel(const int* __restrict__ batch) {
    int idx = blockIdx.x * blockDim.x + threadIdx.x;
    if (idx >= N_NODES * H3) return;
    int i = idx >> 7;        // H3 = 128
    int f = idx & 127;
    int g = batch[i];
    atomicAdd(&g_pool[g * H3 + f], g_act[(size_t)i * H3 + f]);
    if (f == 0) atomicAdd(&g_cnt[g], 1.0f);
}

__global__ void final_linear_kernel(const float* __restrict__ Wo,
                                    const float* __restrict__ bo,
                                    float* __restrict__ out) {
    int t = blockIdx.x * blockDim.x + threadIdx.x;
    if (t >= N_GRAPHS * N_CLS) return;
    int g = t / N_CLS;
    int c = t % N_CLS;
    float inv_cnt = 1.0f / fmaxf(g_cnt[g], 1.0f);
    float s = 0.0f;
    #pragma unroll 8
    for (int f = 0; f < H3; f++)
        s += g_pool[g * H3 + f] * Wo[f * N_CLS + c];
    out[t] = s * inv_cnt + bo[c];
}

// ------------------------ host orchestration ------------------------
static void run_layer(const float* A, const float* W,
                      const float* gamma, const float* beta,
                      int K, int F, const int* ei) {
    dim3 grid(F / 64, (N_NODES + 63) / 64);
    gemm_selfloop_kernel<<<grid, 256>>>(A, W, N_NODES, K, F);

    int fg_log2 = (F == 512) ? 7 : (F == 256) ? 6 : 5;
    int total_s = N_EDGES << fg_log2;
    scatter_edges_kernel<<<(total_s + 255) / 256, 256>>>(ei, F, fg_log2, total_s);

    zero_stats_kernel<<<1, F>>>();
    bn_stats_kernel<<<200, F>>>(F);
    bn_finalize_kernel<<<1, F>>>(gamma, beta);

    int total_e = N_NODES * F;
    bn_apply_relu_kernel<<<(total_e + 255) / 256, 256>>>(F - 1, total_e);
}

extern "C" void kernel_launch(void* const* d_in, const int* in_sizes, int n_in,
                              void* d_out, int out_size) {
    const float* x     = (const float*)d_in[0];
    const int*   ei    = (const int*)d_in[1];
    const int*   batch = (const int*)d_in[2];
    const float* W1 = (const float*)d_in[3];
    const float* g1 = (const float*)d_in[5];
    const float* be1 = (const float*)d_in[6];
    const float* W2 = (const float*)d_in[7];
    const float* g2 = (const float*)d_in[9];
    const float* be2 = (const float*)d_in[10];
    const float* W3 = (const float*)d_in[11];
    const float* g3 = (const float*)d_in[13];
    const float* be3 = (const float*)d_in[14];
    const float* Wo = (const float*)d_in[15];
    const float* bo = (const float*)d_in[16];
    float* out = (float*)d_out;

    void* actp = nullptr;
    cudaGetSymbolAddress(&actp, g_act);
    const float* act = (const float*)actp;

    // degree / dinv (shared by all layers; deg depends only on targets)
    init_deg_kernel<<<(N_NODES + 255) / 256, 256>>>();
    count_deg_kernel<<<(N_EDGES + 255) / 256, 256>>>(ei);
    finalize_dinv_kernel<<<(N_NODES + 255) / 256, 256>>>();

    // 3 GCN layers (BN bias b1/b2/b3 cancels under mean-subtraction; omitted)
    run_layer(x,   W1, g1, be1, F_IN, H1, ei);
    run_layer(act, W2, g2, be2, H1,   H2, ei);
    run_layer(act, W3, g3, be3, H2,   H3, ei);

    // global mean pool + output head
    zero_pool_kernel<<<(N_GRAPHS * H3 + 255) / 256, 256>>>();
    pool_accum_kernel<<<(N_NODES * H3 + 255) / 256, 256>>>(batch);
    final_linear_kernel<<<(N_GRAPHS * N_CLS + 255) / 256, 256>>>(Wo, bo, out);
}

// round 2
// speedup vs baseline: 2.0467x; 2.0467x over previous
#include <cuda_runtime.h>
#include <math.h>

#define N_NODES 50000
#define N_EDGES 800000
#define N_GRAPHS 64
#define F_IN 128
#define H1 512
#define H2 256
#define H3 128
#define N_CLS 10
#define BN_EPS 1e-5f
#define HMAX 512

// ------------------------ scratch (device globals; no allocs) ------------------------
__device__ float  g_deg[N_NODES];                    // dinv
__device__ int    g_counts[N_NODES];                 // in-degree (no self-loop)
__device__ int    g_cur[N_NODES];                    // fill cursors
__device__ int    g_offs[N_NODES + 1];               // CSR offsets (by target)
__device__ int    g_csr_src[N_EDGES];                // source node per CSR slot
__device__ float  g_csr_norm[N_EDGES];               // dinv[src]*dinv[dst] per CSR slot
__device__ float  g_h  [(size_t)N_NODES * HMAX];     // h = A @ W
__device__ float  g_agg[(size_t)N_NODES * HMAX];     // aggregated messages
__device__ float  g_act[(size_t)N_NODES * HMAX];     // relu(bn(agg))
__device__ double g_sum[HMAX];
__device__ double g_sumsq[HMAX];
__device__ float  g_scale[HMAX];
__device__ float  g_shift[HMAX];
__device__ float  g_pool[N_GRAPHS * H3];
__device__ float  g_cnt [N_GRAPHS];

// ------------------------ CSR construction ------------------------
__global__ void zero_counts_kernel() {
    int i = blockIdx.x * blockDim.x + threadIdx.x;
    if (i < N_NODES) { g_counts[i] = 0; g_cur[i] = 0; }
}

__global__ void count_deg_kernel(const int* __restrict__ ei) {
    int e = blockIdx.x * blockDim.x + threadIdx.x;
    if (e < N_EDGES) atomicAdd(&g_counts[ei[N_EDGES + e]], 1);  // target = col
}

__global__ void finalize_dinv_kernel() {
    int i = blockIdx.x * blockDim.x + threadIdx.x;
    if (i < N_NODES) g_deg[i] = rsqrtf((float)g_counts[i] + 1.0f);  // +1 self-loop
}

// single block, 1024 threads: exclusive scan of counts -> offsets
__global__ void scan_offsets_kernel() {
    __shared__ int part[1024];
    int t = threadIdx.x;
    const int PER = (N_NODES + 1023) / 1024;   // 49
    int beg = t * PER;
    int end = min(beg + PER, N_NODES);
    int s = 0;
    for (int i = beg; i < end; i++) s += g_counts[i];
    part[t] = s;
    __syncthreads();
    // Hillis-Steele inclusive scan
    for (int d = 1; d < 1024; d <<= 1) {
        int v = (t >= d) ? part[t - d] : 0;
        __syncthreads();
        part[t] += v;
        __syncthreads();
    }
    int run = (t > 0) ? part[t - 1] : 0;       // exclusive prefix
    for (int i = beg; i < end; i++) {
        g_offs[i] = run;
        run += g_counts[i];
    }
    if (t == 0) g_offs[N_NODES] = N_EDGES;
}

__global__ void fill_csr_kernel(const int* __restrict__ ei) {
    int e = blockIdx.x * blockDim.x + threadIdx.x;
    if (e >= N_EDGES) return;
    int r = ei[e];
    int c = ei[N_EDGES + e];
    int pos = g_offs[c] + atomicAdd(&g_cur[c], 1);
    g_csr_src[pos] = r;
    g_csr_norm[pos] = g_deg[r] * g_deg[c];
}

// ------------------------ GEMM: g_h = A @ W  (BM=128, BN=64, BK=16; 8x4/thread) ------------------------
__global__ void gemm_kernel(const float* __restrict__ A,
                            const float* __restrict__ B,
                            int M, int K, int N) {
    __shared__ float sA[16][132];   // [k][m], pad for STS conflicts
    __shared__ float sB[16][64];    // [k][n]

    int t  = threadIdx.x;           // 0..255
    int tx = t & 15;                // n-dir (x4)
    int ty = t >> 4;                // m-dir (x8)
    int bm = blockIdx.y * 128;
    int bn = blockIdx.x * 64;

    float acc[8][4] = {};

    for (int k0 = 0; k0 < K; k0 += 16) {
        #pragma unroll
        for (int i = 0; i < 8; i++) {
            int idx = t + i * 256;          // 2048: 128m x 16k
            int m   = idx >> 4;
            int kk  = idx & 15;
            int gm  = bm + m;
            sA[kk][m] = (gm < M) ? A[(size_t)gm * K + k0 + kk] : 0.0f;
        }
        #pragma unroll
        for (int i = 0; i < 4; i++) {
            int idx = t + i * 256;          // 1024: 16k x 64n
            int n   = idx & 63;
            int kk  = idx >> 6;
            sB[kk][n] = B[(size_t)(k0 + kk) * N + bn + n];
        }
        __syncthreads();

        #pragma unroll
        for (int kk = 0; kk < 16; kk++) {
            float4 b4 = *(const float4*)&sB[kk][tx * 4];
            float4 a0 = *(const float4*)&sA[kk][ty * 8];
            float4 a1 = *(const float4*)&sA[kk][ty * 8 + 4];
            float a[8] = {a0.x, a0.y, a0.z, a0.w, a1.x, a1.y, a1.z, a1.w};
            float b[4] = {b4.x, b4.y, b4.z, b4.w};
            #pragma unroll
            for (int i = 0; i < 8; i++)
                #pragma unroll
                for (int j = 0; j < 4; j++)
                    acc[i][j] += a[i] * b[j];
        }
        __syncthreads();
    }

    #pragma unroll
    for (int i = 0; i < 8; i++) {
        int m = bm + ty * 8 + i;
        if (m >= M) continue;
        float4 v = make_float4(acc[i][0], acc[i][1], acc[i][2], acc[i][3]);
        *(float4*)&g_h[(size_t)m * N + bn + tx * 4] = v;
    }
}

// ------------------------ CSR gather: agg[c] = h[c]*dinv^2 + sum h[src]*norm ------------------------
// one warp per (node, 128-feature chunk); grid = (nodes/8, F/128), block = 256
__global__ void gather_kernel(int F) {
    int lane = threadIdx.x & 31;
    int node = blockIdx.x * 8 + (threadIdx.x >> 5);
    if (node >= N_NODES) return;
    int f0 = (blockIdx.y << 7) + lane * 4;

    float di = g_deg[node];
    float sl = di * di;
    float4 acc = *(const float4*)&g_h[(size_t)node * F + f0];
    acc.x *= sl; acc.y *= sl; acc.z *= sl; acc.w *= sl;

    int j   = g_offs[node];
    int end = g_offs[node + 1];
    for (; j + 1 < end; j += 2) {
        int   s0 = g_csr_src[j];
        int   s1 = g_csr_src[j + 1];
        float n0 = g_csr_norm[j];
        float n1 = g_csr_norm[j + 1];
        float4 h0 = *(const float4*)&g_h[(size_t)s0 * F + f0];
        float4 h1 = *(const float4*)&g_h[(size_t)s1 * F + f0];
        acc.x += h0.x * n0; acc.y += h0.y * n0; acc.z += h0.z * n0; acc.w += h0.w * n0;
        acc.x += h1.x * n1; acc.y += h1.y * n1; acc.z += h1.z * n1; acc.w += h1.w * n1;
    }
    if (j < end) {
        int   s0 = g_csr_src[j];
        float n0 = g_csr_norm[j];
        float4 h0 = *(const float4*)&g_h[(size_t)s0 * F + f0];
        acc.x += h0.x * n0; acc.y += h0.y * n0; acc.z += h0.z * n0; acc.w += h0.w * n0;
    }
    *(float4*)&g_agg[(size_t)node * F + f0] = acc;
}

// ------------------------ BatchNorm ------------------------
__global__ void zero_stats_kernel() {
    int f = threadIdx.x;
    g_sum[f] = 0.0;
    g_sumsq[f] = 0.0;
}

__global__ void bn_stats_kernel(int F) {
    int f  = threadIdx.x;
    int r0 = blockIdx.x * 250;
    double s = 0.0, s2 = 0.0;
    for (int r = r0; r < r0 + 250; r++) {
        float v = g_agg[(size_t)r * F + f];
        s  += (double)v;
        s2 += (double)v * (double)v;
    }
    atomicAdd(&g_sum[f], s);
    atomicAdd(&g_sumsq[f], s2);
}

__global__ void bn_finalize_kernel(const float* __restrict__ gamma,
                                   const float* __restrict__ beta) {
    int f = threadIdx.x;
    double mean = g_sum[f] * (1.0 / N_NODES);
    double var  = g_sumsq[f] * (1.0 / N_NODES) - mean * mean;
    float scale = gamma[f] * rsqrtf((float)var + BN_EPS);
    g_scale[f] = scale;
    g_shift[f] = beta[f] - (float)mean * scale;
}

__global__ void bn_apply_relu_kernel(int mask, int total) {
    int idx = blockIdx.x * blockDim.x + threadIdx.x;
    if (idx >= total) return;
    int f = idx & mask;
    g_act[idx] = fmaxf(g_agg[idx] * g_scale[f] + g_shift[f], 0.0f);
}

// ------------------------ global mean pool + output linear ------------------------
__global__ void zero_pool_kernel() {
    int i = blockIdx.x * blockDim.x + threadIdx.x;
    if (i < N_GRAPHS * H3) g_pool[i] = 0.0f;
    if (i < N_GRAPHS) g_cnt[i] = 0.0f;
}

__global__ void pool_accum_kernel(const int* __restrict__ batch) {
    int idx = blockIdx.x * blockDim.x + threadIdx.x;
    if (idx >= N_NODES * H3) return;
    int i = idx >> 7;        // H3 = 128
    int f = idx & 127;
    int g = batch[i];
    atomicAdd(&g_pool[g * H3 + f], g_act[(size_t)i * H3 + f]);
    if (f == 0) atomicAdd(&g_cnt[g], 1.0f);
}

__global__ void final_linear_kernel(const float* __restrict__ Wo,
                                    const float* __restrict__ bo,
                                    float* __restrict__ out) {
    int t = blockIdx.x * blockDim.x + threadIdx.x;
    if (t >= N_GRAPHS * N_CLS) return;
    int g = t / N_CLS;
    int c = t % N_CLS;
    float inv_cnt = 1.0f / fmaxf(g_cnt[g], 1.0f);
    float s = 0.0f;
    #pragma unroll 8
    for (int f = 0; f < H3; f++)
        s += g_pool[g * H3 + f] * Wo[f * N_CLS + c];
    out[t] = s * inv_cnt + bo[c];
}

// ------------------------ host orchestration ------------------------
static void run_layer(const float* A, const float* W,
                      const float* gamma, const float* beta,
                      int K, int F) {
    dim3 ggrid(F / 64, (N_NODES + 127) / 128);
    gemm_kernel<<<ggrid, 256>>>(A, W, N_NODES, K, F);

    dim3 sgrid((N_NODES + 7) / 8, F / 128);
    gather_kernel<<<sgrid, 256>>>(F);

    zero_stats_kernel<<<1, F>>>();
    bn_stats_kernel<<<200, F>>>(F);
    bn_finalize_kernel<<<1, F>>>(gamma, beta);

    int total_e = N_NODES * F;
    bn_apply_relu_kernel<<<(total_e + 255) / 256, 256>>>(F - 1, total_e);
}

extern "C" void kernel_launch(void* const* d_in, const int* in_sizes, int n_in,
                              void* d_out, int out_size) {
    const float* x     = (const float*)d_in[0];
    const int*   ei    = (const int*)d_in[1];
    const int*   batch = (const int*)d_in[2];
    const float* W1 = (const float*)d_in[3];
    const float* g1 = (const float*)d_in[5];
    const float* be1 = (const float*)d_in[6];
    const float* W2 = (const float*)d_in[7];
    const float* g2 = (const float*)d_in[9];
    const float* be2 = (const float*)d_in[10];
    const float* W3 = (const float*)d_in[11];
    const float* g3 = (const float*)d_in[13];
    const float* be3 = (const float*)d_in[14];
    const float* Wo = (const float*)d_in[15];
    const float* bo = (const float*)d_in[16];
    float* out = (float*)d_out;

    void* actp = nullptr;
    cudaGetSymbolAddress(&actp, g_act);
    const float* act = (const float*)actp;

    // CSR build (by target) + dinv — shared by all 3 layers
    zero_counts_kernel<<<(N_NODES + 255) / 256, 256>>>();
    count_deg_kernel<<<(N_EDGES + 255) / 256, 256>>>(ei);
    finalize_dinv_kernel<<<(N_NODES + 255) / 256, 256>>>();
    scan_offsets_kernel<<<1, 1024>>>();
    fill_csr_kernel<<<(N_EDGES + 255) / 256, 256>>>(ei);

    // 3 GCN layers (BN linear bias cancels under mean-subtraction; omitted)
    run_layer(x,   W1, g1, be1, F_IN, H1);
    run_layer(act, W2, g2, be2, H1,   H2);
    run_layer(act, W3, g3, be3, H2,   H3);

    // global mean pool + output head
    zero_pool_kernel<<<(N_GRAPHS * H3 + 255) / 256, 256>>>();
    pool_accum_kernel<<<(N_NODES * H3 + 255) / 256, 256>>>(batch);
    final_linear_kernel<<<(N_GRAPHS * N_CLS + 255) / 256, 256>>>(Wo, bo, out);
}

// round 3
// speedup vs baseline: 3.2258x; 1.5761x over previous
#include <cuda_runtime.h>
#include <math.h>

#define N_NODES 50000
#define N_EDGES 800000
#define N_GRAPHS 64
#define F_IN 128
#define H1 512
#define H2 256
#define H3 128
#define N_CLS 10
#define BN_EPS 1e-5f
#define HMAX 512
#define SCAN_NB 49   // ceil(50000/1024)

// ------------------------ scratch (device globals; no allocs) ------------------------
__device__ float  g_deg[N_NODES];                    // dinv
__device__ int    g_counts[N_NODES];
__device__ int    g_cur[N_NODES];
__device__ int    g_bsum[64];
__device__ int    g_bbase[64];
__device__ int    g_offs[N_NODES + 1];
__device__ int    g_csr_src[N_EDGES];
__device__ float  g_csr_norm[N_EDGES];
__device__ float  g_h  [(size_t)N_NODES * HMAX];
__device__ float  g_agg[(size_t)N_NODES * HMAX];
__device__ float  g_sumf[HMAX];                      // zero-init; re-zeroed by bn_finalize
__device__ float  g_sqf [HMAX];
__device__ float  g_scale[HMAX];
__device__ float  g_shift[HMAX];
__device__ float  g_pool[N_GRAPHS * H3];
__device__ float  g_cnt [N_GRAPHS];

// ------------------------ CSR construction ------------------------
__global__ void zero_counts_kernel() {
    int i = blockIdx.x * blockDim.x + threadIdx.x;
    if (i < N_NODES) { g_counts[i] = 0; g_cur[i] = 0; }
}

__global__ void count_deg_kernel(const int* __restrict__ ei) {
    int e = blockIdx.x * blockDim.x + threadIdx.x;
    if (e < N_EDGES) atomicAdd(&g_counts[ei[N_EDGES + e]], 1);
}

__global__ void finalize_dinv_kernel() {
    int i = blockIdx.x * blockDim.x + threadIdx.x;
    if (i < N_NODES) g_deg[i] = rsqrtf((float)g_counts[i] + 1.0f);
}

__global__ void partial_sum_kernel() {
    __shared__ int s[1024];
    int t = threadIdx.x;
    int i = blockIdx.x * 1024 + t;
    s[t] = (i < N_NODES) ? g_counts[i] : 0;
    __syncthreads();
    for (int st = 512; st > 0; st >>= 1) {
        if (t < st) s[t] += s[t + st];
        __syncthreads();
    }
    if (t == 0) g_bsum[blockIdx.x] = s[0];
}

__global__ void scan_bsum_kernel() {
    __shared__ int s[64];
    int t = threadIdx.x;
    int v0 = (t < SCAN_NB) ? g_bsum[t] : 0;
    s[t] = v0;
    __syncthreads();
    for (int d = 1; d < 64; d <<= 1) {
        int v = (t >= d) ? s[t - d] : 0;
        __syncthreads();
        s[t] += v;
        __syncthreads();
    }
    if (t < SCAN_NB) g_bbase[t] = s[t] - v0;   // exclusive
    if (t == 0) g_offs[N_NODES] = N_EDGES;
}

__global__ void offsets_kernel() {
    __shared__ int s[1024];
    int t = threadIdx.x;
    int i = blockIdx.x * 1024 + t;
    int c = (i < N_NODES) ? g_counts[i] : 0;
    s[t] = c;
    __syncthreads();
    for (int d = 1; d < 1024; d <<= 1) {
        int v = (t >= d) ? s[t - d] : 0;
        __syncthreads();
        s[t] += v;
        __syncthreads();
    }
    if (i < N_NODES) g_offs[i] = g_bbase[blockIdx.x] + s[t] - c;
}

__global__ void fill_csr_kernel(const int* __restrict__ ei) {
    int e = blockIdx.x * blockDim.x + threadIdx.x;
    if (e >= N_EDGES) return;
    int r = ei[e];
    int c = ei[N_EDGES + e];
    int pos = g_offs[c] + atomicAdd(&g_cur[c], 1);
    g_csr_src[pos] = r;
    g_csr_norm[pos] = g_deg[r] * g_deg[c];
}

// ------------------------ GEMM: g_h = f(A) @ W ------------------------
// 128x128x8 tile, 256 threads, 8x8/thread (quadrant layout), double buffered.
// APPLY_BN folds relu(a*scale+shift) into the A-load (previous layer's BN).
template<bool APPLY_BN>
__global__ void __launch_bounds__(256, 2)
gemm_kernel(const float* __restrict__ A, const float* __restrict__ B,
            int M, int K, int N) {
    __shared__ float sA[2][8][132];
    __shared__ float sB[2][8][128];
    __shared__ float sSc[HMAX], sSh[HMAX];

    int t  = threadIdx.x;
    int tx = t & 15;
    int ty = t >> 4;
    int bm = blockIdx.y * 128;
    int bc = blockIdx.x * 128;

    if (APPLY_BN) {
        for (int i = t; i < K; i += 256) { sSc[i] = g_scale[i]; sSh[i] = g_shift[i]; }
        __syncthreads();
    }

    // A-load mapping: one float4 per thread per tile
    int am = t >> 1;                 // row within tile (0..127)
    int ah = (t & 1) * 4;            // k-offset (0 or 4)
    bool arow_ok = (bm + am) < M;
    const float* Aptr = A + (size_t)(bm + am) * K + ah;
    // B-load mapping
    int kb = t >> 5;                 // k row (0..7)
    int nb = (t & 31) * 4;           // col offset
    const float* Bptr = B + (size_t)kb * N + bc + nb;

    float acc[8][8];
    #pragma unroll
    for (int i = 0; i < 8; i++)
        #pragma unroll
        for (int j = 0; j < 8; j++) acc[i][j] = 0.0f;

    // prologue: tile k0=0
    float4 ar = make_float4(0.f, 0.f, 0.f, 0.f);
    if (arow_ok) ar = *(const float4*)(Aptr);
    float4 br = *(const float4*)(Bptr);
    if (APPLY_BN && arow_ok) {
        ar.x = fmaxf(fmaf(ar.x, sSc[ah + 0], sSh[ah + 0]), 0.f);
        ar.y = fmaxf(fmaf(ar.y, sSc[ah + 1], sSh[ah + 1]), 0.f);
        ar.z = fmaxf(fmaf(ar.z, sSc[ah + 2], sSh[ah + 2]), 0.f);
        ar.w = fmaxf(fmaf(ar.w, sSc[ah + 3], sSh[ah + 3]), 0.f);
    }
    sA[0][ah + 0][am] = ar.x; sA[0][ah + 1][am] = ar.y;
    sA[0][ah + 2][am] = ar.z; sA[0][ah + 3][am] = ar.w;
    *(float4*)&sB[0][kb][nb] = br;
    __syncthreads();

    int buf = 0;
    for (int k0 = 0; k0 < K; k0 += 8) {
        int kn = k0 + 8;
        bool more = kn < K;
        if (more) {
            ar = make_float4(0.f, 0.f, 0.f, 0.f);
            if (arow_ok) ar = *(const float4*)(Aptr + kn);
            br = *(const float4*)(Bptr + (size_t)kn * N);
            if (APPLY_BN && arow_ok) {
                ar.x = fmaxf(fmaf(ar.x, sSc[kn + ah + 0], sSh[kn + ah + 0]), 0.f);
                ar.y = fmaxf(fmaf(ar.y, sSc[kn + ah + 1], sSh[kn + ah + 1]), 0.f);
                ar.z = fmaxf(fmaf(ar.z, sSc[kn + ah + 2], sSh[kn + ah + 2]), 0.f);
                ar.w = fmaxf(fmaf(ar.w, sSc[kn + ah + 3], sSh[kn + ah + 3]), 0.f);
            }
        }

        #pragma unroll
        for (int kk = 0; kk < 8; kk++) {
            float4 a0 = *(const float4*)&sA[buf][kk][ty * 4];
            float4 a1 = *(const float4*)&sA[buf][kk][64 + ty * 4];
            float4 b0 = *(const float4*)&sB[buf][kk][tx * 4];
            float4 b1 = *(const float4*)&sB[buf][kk][64 + tx * 4];
            float a[8] = {a0.x, a0.y, a0.z, a0.w, a1.x, a1.y, a1.z, a1.w};
            float b[8] = {b0.x, b0.y, b0.z, b0.w, b1.x, b1.y, b1.z, b1.w};
            #pragma unroll
            for (int i = 0; i < 8; i++)
                #pragma unroll
                for (int j = 0; j < 8; j++)
                    acc[i][j] += a[i] * b[j];
        }

        if (more) {
            int nb2 = buf ^ 1;
            sA[nb2][ah + 0][am] = ar.x; sA[nb2][ah + 1][am] = ar.y;
            sA[nb2][ah + 2][am] = ar.z; sA[nb2][ah + 3][am] = ar.w;
            *(float4*)&sB[nb2][kb][nb] = br;
        }
        __syncthreads();
        buf ^= 1;
    }

    // epilogue: quadrant store
    #pragma unroll
    for (int i = 0; i < 8; i++) {
        int m = bm + ((i < 4) ? (ty * 4 + i) : (64 + ty * 4 + i - 4));
        if (m >= M) continue;
        float4 v0 = make_float4(acc[i][0], acc[i][1], acc[i][2], acc[i][3]);
        float4 v1 = make_float4(acc[i][4], acc[i][5], acc[i][6], acc[i][7]);
        *(float4*)&g_h[(size_t)m * N + bc + tx * 4]      = v0;
        *(float4*)&g_h[(size_t)m * N + bc + 64 + tx * 4] = v1;
    }
}

// ------------------------ CSR gather + fused BN stats ------------------------
// one warp per (node, 128-feature chunk); grid=(6250, F/128), block=256 (8 nodes)
__global__ void gather_stats_kernel(int F) {
    __shared__ float s_ps[8][128];
    __shared__ float s_pq[8][128];

    int t    = threadIdx.x;
    int lane = t & 31;
    int w    = t >> 5;
    int node = blockIdx.x * 8 + w;          // always < N_NODES (50000 = 6250*8)
    int fb   = blockIdx.y << 7;
    int f0   = fb + lane * 4;

    float di = g_deg[node];
    float sl = di * di;
    float4 acc = *(const float4*)&g_h[(size_t)node * F + f0];
    acc.x *= sl; acc.y *= sl; acc.z *= sl; acc.w *= sl;

    int j   = g_offs[node];
    int end = g_offs[node + 1];
    for (; j + 1 < end; j += 2) {
        int   s0 = g_csr_src[j];
        int   s1 = g_csr_src[j + 1];
        float n0 = g_csr_norm[j];
        float n1 = g_csr_norm[j + 1];
        float4 h0 = *(const float4*)&g_h[(size_t)s0 * F + f0];
        float4 h1 = *(const float4*)&g_h[(size_t)s1 * F + f0];
        acc.x += h0.x * n0; acc.y += h0.y * n0; acc.z += h0.z * n0; acc.w += h0.w * n0;
        acc.x += h1.x * n1; acc.y += h1.y * n1; acc.z += h1.z * n1; acc.w += h1.w * n1;
    }
    if (j < end) {
        int   s0 = g_csr_src[j];
        float n0 = g_csr_norm[j];
        float4 h0 = *(const float4*)&g_h[(size_t)s0 * F + f0];
        acc.x += h0.x * n0; acc.y += h0.y * n0; acc.z += h0.z * n0; acc.w += h0.w * n0;
    }
    *(float4*)&g_agg[(size_t)node * F + f0] = acc;

    // fused BN statistics: per-block partial, then one RED per feature
    *(float4*)&s_ps[w][lane * 4] = acc;
    *(float4*)&s_pq[w][lane * 4] = make_float4(acc.x * acc.x, acc.y * acc.y,
                                               acc.z * acc.z, acc.w * acc.w);
    __syncthreads();
    if (t < 128) {
        float s = 0.f;
        #pragma unroll
        for (int ww = 0; ww < 8; ww++) s += s_ps[ww][t];
        atomicAdd(&g_sumf[fb + t], s);
    } else {
        int t2 = t - 128;
        float s = 0.f;
        #pragma unroll
        for (int ww = 0; ww < 8; ww++) s += s_pq[ww][t2];
        atomicAdd(&g_sqf[fb + t2], s);
    }
}

// compute scale/shift, then re-zero the accumulators for the next use/replay
__global__ void bn_finalize_kernel(const float* __restrict__ gamma,
                                   const float* __restrict__ beta) {
    int f = threadIdx.x;
    double mean = (double)g_sumf[f] * (1.0 / N_NODES);
    double var  = (double)g_sqf[f] * (1.0 / N_NODES) - mean * mean;
    float scale = gamma[f] * rsqrtf((float)var + BN_EPS);
    g_scale[f] = scale;
    g_shift[f] = beta[f] - (float)mean * scale;
    g_sumf[f] = 0.f;
    g_sqf[f]  = 0.f;
}

// ------------------------ pool (fused BN3+ReLU, run-length atomics) ------------------------
__global__ void zero_pool_kernel() {
    int i = blockIdx.x * blockDim.x + threadIdx.x;
    if (i < N_GRAPHS * H3) g_pool[i] = 0.0f;
    if (i < N_GRAPHS) g_cnt[i] = 0.0f;
}

// 128 threads/block, 32 nodes/block; batch is sorted -> few graph transitions
__global__ void pool_kernel(const int* __restrict__ batch) {
    int f  = threadIdx.x;
    int n0 = blockIdx.x * 32;
    int ne = min(n0 + 32, N_NODES);
    float sc = g_scale[f], sh = g_shift[f];
    int curg = batch[n0];
    float run = 0.f, cnt = 0.f;
    for (int n = n0; n < ne; n++) {
        int g = batch[n];
        if (g != curg) {
            atomicAdd(&g_pool[curg * H3 + f], run);
            if (f == 0) atomicAdd(&g_cnt[curg], cnt);
            run = 0.f; cnt = 0.f; curg = g;
        }
        float v = g_agg[(size_t)n * H3 + f];
        run += fmaxf(fmaf(v, sc, sh), 0.f);
        cnt += 1.f;
    }
    atomicAdd(&g_pool[curg * H3 + f], run);
    if (f == 0) atomicAdd(&g_cnt[curg], cnt);
}

__global__ void final_linear_kernel(const float* __restrict__ Wo,
                                    const float* __restrict__ bo,
                                    float* __restrict__ out) {
    int t = blockIdx.x * blockDim.x + threadIdx.x;
    if (t >= N_GRAPHS * N_CLS) return;
    int g = t / N_CLS;
    int c = t % N_CLS;
    float inv_cnt = 1.0f / fmaxf(g_cnt[g], 1.0f);
    float s = 0.0f;
    #pragma unroll 8
    for (int f = 0; f < H3; f++)
        s += g_pool[g * H3 + f] * Wo[f * N_CLS + c];
    out[t] = s * inv_cnt + bo[c];
}

// ------------------------ host orchestration ------------------------
extern "C" void kernel_launch(void* const* d_in, const int* in_sizes, int n_in,
                              void* d_out, int out_size) {
    const float* x     = (const float*)d_in[0];
    const int*   ei    = (const int*)d_in[1];
    const int*   batch = (const int*)d_in[2];
    const float* W1 = (const float*)d_in[3];
    const float* g1 = (const float*)d_in[5];
    const float* be1 = (const float*)d_in[6];
    const float* W2 = (const float*)d_in[7];
    const float* g2 = (const float*)d_in[9];
    const float* be2 = (const float*)d_in[10];
    const float* W3 = (const float*)d_in[11];
    const float* g3 = (const float*)d_in[13];
    const float* be3 = (const float*)d_in[14];
    const float* Wo = (const float*)d_in[15];
    const float* bo = (const float*)d_in[16];
    float* out = (float*)d_out;

    void* aggp = nullptr;
    cudaGetSymbolAddress(&aggp, g_agg);
    const float* agg = (const float*)aggp;

    // CSR build (by target) + dinv
    zero_counts_kernel<<<(N_NODES + 255) / 256, 256>>>();
    count_deg_kernel<<<(N_EDGES + 255) / 256, 256>>>(ei);
    finalize_dinv_kernel<<<(N_NODES + 255) / 256, 256>>>();
    partial_sum_kernel<<<SCAN_NB, 1024>>>();
    scan_bsum_kernel<<<1, 64>>>();
    offsets_kernel<<<SCAN_NB, 1024>>>();
    fill_csr_kernel<<<(N_EDGES + 255) / 256, 256>>>(ei);

    const int MB = (N_NODES + 127) / 128;   // 391

    // layer 1: h = x @ W1 ; gather+stats ; finalize (scale1/shift1)
    gemm_kernel<false><<<dim3(H1 / 128, MB), 256>>>(x, W1, N_NODES, F_IN, H1);
    gather_stats_kernel<<<dim3(N_NODES / 8, H1 / 128), 256>>>(H1);
    bn_finalize_kernel<<<1, H1>>>(g1, be1);

    // layer 2: h = relu(bn(agg)) @ W2 (BN folded into A-load)
    gemm_kernel<true><<<dim3(H2 / 128, MB), 256>>>(agg, W2, N_NODES, H1, H2);
    gather_stats_kernel<<<dim3(N_NODES / 8, H2 / 128), 256>>>(H2);
    bn_finalize_kernel<<<1, H2>>>(g2, be2);

    // layer 3
    gemm_kernel<true><<<dim3(H3 / 128, MB), 256>>>(agg, W3, N_NODES, H2, H3);
    gather_stats_kernel<<<dim3(N_NODES / 8, H3 / 128), 256>>>(H3);
    bn_finalize_kernel<<<1, H3>>>(g3, be3);

    // pool (BN3+ReLU fused) + output head
    zero_pool_kernel<<<(N_GRAPHS * H3 + 255) / 256, 256>>>();
    pool_kernel<<<(N_NODES + 31) / 32, 128>>>(batch);
    final_linear_kernel<<<(N_GRAPHS * N_CLS + 255) / 256, 256>>>(Wo, bo, out);
}

// round 4
// speedup vs baseline: 4.5777x; 1.4191x over previous
#include <cuda_runtime.h>
#include <math.h>
#include <stdint.h>

#define N_NODES 50000
#define N_EDGES 800000
#define N_GRAPHS 64
#define F_IN 128
#define H1 512
#define H2 256
#define H3 128
#define N_CLS 10
#define BN_EPS 1e-5f
#define HMAX 512
#define SCAN_NB 49   // ceil(50000/1024)

// ------------------------ scratch (device globals; no allocs) ------------------------
__device__ float  g_deg[N_NODES];                    // dinv
__device__ int    g_counts[N_NODES];
__device__ int    g_cur[N_NODES];
__device__ int    g_bsum[64];
__device__ int    g_bbase[64];
__device__ int    g_offs[N_NODES + 1];
__device__ int    g_csr_src[N_EDGES];
__device__ float  g_csr_norm[N_EDGES];
__device__ float  g_h  [(size_t)N_NODES * HMAX];
__device__ float  g_agg[(size_t)N_NODES * HMAX];
__device__ float  g_sumf[HMAX];                      // zero-init; re-zeroed by bn_finalize
__device__ float  g_sqf [HMAX];
__device__ float  g_scale[HMAX];
__device__ float  g_shift[HMAX];
__device__ float  g_pool[N_GRAPHS * H3];
__device__ float  g_cnt [N_GRAPHS];

// ------------------------ CSR construction ------------------------
__global__ void zero_counts_kernel() {
    int i = blockIdx.x * blockDim.x + threadIdx.x;
    if (i < N_NODES) { g_counts[i] = 0; g_cur[i] = 0; }
}

__global__ void count_deg_kernel(const int* __restrict__ ei) {
    int e = blockIdx.x * blockDim.x + threadIdx.x;
    if (e < N_EDGES) atomicAdd(&g_counts[ei[N_EDGES + e]], 1);
}

__global__ void finalize_dinv_kernel() {
    int i = blockIdx.x * blockDim.x + threadIdx.x;
    if (i < N_NODES) g_deg[i] = rsqrtf((float)g_counts[i] + 1.0f);
}

__global__ void partial_sum_kernel() {
    __shared__ int s[1024];
    int t = threadIdx.x;
    int i = blockIdx.x * 1024 + t;
    s[t] = (i < N_NODES) ? g_counts[i] : 0;
    __syncthreads();
    for (int st = 512; st > 0; st >>= 1) {
        if (t < st) s[t] += s[t + st];
        __syncthreads();
    }
    if (t == 0) g_bsum[blockIdx.x] = s[0];
}

__global__ void scan_bsum_kernel() {
    __shared__ int s[64];
    int t = threadIdx.x;
    int v0 = (t < SCAN_NB) ? g_bsum[t] : 0;
    s[t] = v0;
    __syncthreads();
    for (int d = 1; d < 64; d <<= 1) {
        int v = (t >= d) ? s[t - d] : 0;
        __syncthreads();
        s[t] += v;
        __syncthreads();
    }
    if (t < SCAN_NB) g_bbase[t] = s[t] - v0;   // exclusive
    if (t == 0) g_offs[N_NODES] = N_EDGES;
}

__global__ void offsets_kernel() {
    __shared__ int s[1024];
    int t = threadIdx.x;
    int i = blockIdx.x * 1024 + t;
    int c = (i < N_NODES) ? g_counts[i] : 0;
    s[t] = c;
    __syncthreads();
    for (int d = 1; d < 1024; d <<= 1) {
        int v = (t >= d) ? s[t - d] : 0;
        __syncthreads();
        s[t] += v;
        __syncthreads();
    }
    if (i < N_NODES) g_offs[i] = g_bbase[blockIdx.x] + s[t] - c;
}

__global__ void fill_csr_kernel(const int* __restrict__ ei) {
    int e = blockIdx.x * blockDim.x + threadIdx.x;
    if (e >= N_EDGES) return;
    int r = ei[e];
    int c = ei[N_EDGES + e];
    int pos = g_offs[c] + atomicAdd(&g_cur[c], 1);
    g_csr_src[pos] = r;
    g_csr_norm[pos] = g_deg[r] * g_deg[c];
}

// ------------------------ tf32 helpers ------------------------
__device__ __forceinline__ uint32_t f2tf32(float f) {
    uint32_t r;
    asm("cvt.rna.tf32.f32 %0, %1;" : "=r"(r) : "f"(f));
    return r;
}

__device__ __forceinline__ void mma_tf32(float4& c, const uint32_t* a,
                                         uint32_t b0, uint32_t b1) {
    asm volatile(
        "mma.sync.aligned.m16n8k8.row.col.f32.tf32.tf32.f32 "
        "{%0,%1,%2,%3}, {%4,%5,%6,%7}, {%8,%9}, {%0,%1,%2,%3};"
        : "+f"(c.x), "+f"(c.y), "+f"(c.z), "+f"(c.w)
        : "r"(a[0]), "r"(a[1]), "r"(a[2]), "r"(a[3]), "r"(b0), "r"(b1));
}

// ------------------------ GEMM: C = f(A) @ W  (tf32 tensor cores, W hi+lo split) ------------------------
// 128x128 block, BK=8, 256 threads (8 warps: 2m x 4n, warp tile 64x32), double buffered.
#define ASTR 12   // sA row stride ([m][k]) — conflict-free fragment loads
#define BSTR 13   // sB row stride ([n][k])

template<bool APPLY_BN>
__global__ void __launch_bounds__(256, 2)
gemm_tf32_kernel(const float* __restrict__ A, const float* __restrict__ B,
                 float* __restrict__ C, int M, int K, int N) {
    __shared__ uint32_t sA [2][128 * ASTR];
    __shared__ uint32_t sBh[2][128 * BSTR];
    __shared__ uint32_t sBl[2][128 * BSTR];
    __shared__ float sSc[HMAX], sSh[HMAX];

    int t    = threadIdx.x;
    int lane = t & 31;
    int warp = t >> 5;
    int g    = lane >> 2;      // groupID
    int tig  = lane & 3;       // threadID_in_group
    int wm   = (warp & 1) * 64;
    int wn   = (warp >> 1) * 32;
    int bm   = blockIdx.y * 128;
    int bcn  = blockIdx.x * 128;

    if (APPLY_BN) {
        for (int i = t; i < K; i += 256) { sSc[i] = g_scale[i]; sSh[i] = g_shift[i]; }
        __syncthreads();
    }

    // loader mappings
    int am = t >> 1, ak = (t & 1) * 4;
    bool arow = (bm + am) < M;
    const float* Ap = A + (size_t)(bm + am) * K + ak;
    int bk = t >> 5, bn4 = (t & 31) * 4;
    const float* Bp = B + (size_t)bk * N + bcn + bn4;

    float4 acc[4][4];
    #pragma unroll
    for (int i = 0; i < 4; i++)
        #pragma unroll
        for (int j = 0; j < 4; j++) acc[i][j] = make_float4(0.f, 0.f, 0.f, 0.f);

    uint4 ua;                   // converted A (4 k-values)
    uint4 ubh, ubl;             // converted B hi/lo

    // --- load + convert one tile (k0) into registers ---
    auto load_tile = [&](int k0) {
        float4 av = make_float4(0.f, 0.f, 0.f, 0.f);
        if (arow) av = *(const float4*)(Ap + k0);
        if (APPLY_BN && arow) {
            av.x = fmaxf(fmaf(av.x, sSc[k0 + ak + 0], sSh[k0 + ak + 0]), 0.f);
            av.y = fmaxf(fmaf(av.y, sSc[k0 + ak + 1], sSh[k0 + ak + 1]), 0.f);
            av.z = fmaxf(fmaf(av.z, sSc[k0 + ak + 2], sSh[k0 + ak + 2]), 0.f);
            av.w = fmaxf(fmaf(av.w, sSc[k0 + ak + 3], sSh[k0 + ak + 3]), 0.f);
        }
        ua.x = f2tf32(av.x); ua.y = f2tf32(av.y);
        ua.z = f2tf32(av.z); ua.w = f2tf32(av.w);

        float4 bv = *(const float4*)(Bp + (size_t)k0 * N);
        ubh.x = f2tf32(bv.x); ubl.x = f2tf32(bv.x - __uint_as_float(ubh.x));
        ubh.y = f2tf32(bv.y); ubl.y = f2tf32(bv.y - __uint_as_float(ubh.y));
        ubh.z = f2tf32(bv.z); ubl.z = f2tf32(bv.z - __uint_as_float(ubh.z));
        ubh.w = f2tf32(bv.w); ubl.w = f2tf32(bv.w - __uint_as_float(ubh.w));
    };

    auto store_tile = [&](int buf) {
        *(uint4*)&sA[buf][am * ASTR + ak] = ua;
        sBh[buf][(bn4 + 0) * BSTR + bk] = ubh.x;
        sBh[buf][(bn4 + 1) * BSTR + bk] = ubh.y;
        sBh[buf][(bn4 + 2) * BSTR + bk] = ubh.z;
        sBh[buf][(bn4 + 3) * BSTR + bk] = ubh.w;
        sBl[buf][(bn4 + 0) * BSTR + bk] = ubl.x;
        sBl[buf][(bn4 + 1) * BSTR + bk] = ubl.y;
        sBl[buf][(bn4 + 2) * BSTR + bk] = ubl.z;
        sBl[buf][(bn4 + 3) * BSTR + bk] = ubl.w;
    };

    load_tile(0);
    store_tile(0);
    __syncthreads();

    int buf = 0;
    for (int k0 = 0; k0 < K; k0 += 8) {
        bool more = (k0 + 8) < K;
        if (more) load_tile(k0 + 8);

        // fragments from current buffer
        uint32_t af[4][4];
        #pragma unroll
        for (int i = 0; i < 4; i++) {
            int r0 = wm + 16 * i;
            af[i][0] = sA[buf][(r0 + g    ) * ASTR + tig    ];
            af[i][1] = sA[buf][(r0 + g + 8) * ASTR + tig    ];
            af[i][2] = sA[buf][(r0 + g    ) * ASTR + tig + 4];
            af[i][3] = sA[buf][(r0 + g + 8) * ASTR + tig + 4];
        }
        #pragma unroll
        for (int j = 0; j < 4; j++) {
            int nb = wn + 8 * j + g;
            uint32_t bh0 = sBh[buf][nb * BSTR + tig    ];
            uint32_t bh1 = sBh[buf][nb * BSTR + tig + 4];
            uint32_t bl0 = sBl[buf][nb * BSTR + tig    ];
            uint32_t bl1 = sBl[buf][nb * BSTR + tig + 4];
            #pragma unroll
            for (int i = 0; i < 4; i++) {
                mma_tf32(acc[i][j], af[i], bh0, bh1);
                mma_tf32(acc[i][j], af[i], bl0, bl1);
            }
        }

        if (more) store_tile(buf ^ 1);
        __syncthreads();
        buf ^= 1;
    }

    // epilogue
    #pragma unroll
    for (int i = 0; i < 4; i++) {
        int m0 = bm + wm + 16 * i + g;
        int m1 = m0 + 8;
        #pragma unroll
        for (int j = 0; j < 4; j++) {
            int n = bcn + wn + 8 * j + 2 * tig;
            if (m0 < M) *(float2*)&C[(size_t)m0 * N + n] = make_float2(acc[i][j].x, acc[i][j].y);
            if (m1 < M) *(float2*)&C[(size_t)m1 * N + n] = make_float2(acc[i][j].z, acc[i][j].w);
        }
    }
}

// ------------------------ CSR gather (+ optional fused BN stats) ------------------------
// one warp per (node, 128-feature chunk); grid=(6250, F/128), block=256 (8 nodes)
template<bool DO_STATS>
__global__ void gather_kernel(const float* __restrict__ src, float* __restrict__ dst, int F) {
    __shared__ float s_ps[8][128];
    __shared__ float s_pq[8][128];

    int t    = threadIdx.x;
    int lane = t & 31;
    int w    = t >> 5;
    int node = blockIdx.x * 8 + w;          // 50000 = 6250*8
    int fb   = blockIdx.y << 7;
    int f0   = fb + lane * 4;

    float di = g_deg[node];
    float sl = di * di;
    float4 acc = *(const float4*)&src[(size_t)node * F + f0];
    acc.x *= sl; acc.y *= sl; acc.z *= sl; acc.w *= sl;

    int j   = g_offs[node];
    int end = g_offs[node + 1];
    for (; j + 1 < end; j += 2) {
        int   s0 = g_csr_src[j];
        int   s1 = g_csr_src[j + 1];
        float n0 = g_csr_norm[j];
        float n1 = g_csr_norm[j + 1];
        float4 h0 = *(const float4*)&src[(size_t)s0 * F + f0];
        float4 h1 = *(const float4*)&src[(size_t)s1 * F + f0];
        acc.x += h0.x * n0; acc.y += h0.y * n0; acc.z += h0.z * n0; acc.w += h0.w * n0;
        acc.x += h1.x * n1; acc.y += h1.y * n1; acc.z += h1.z * n1; acc.w += h1.w * n1;
    }
    if (j < end) {
        int   s0 = g_csr_src[j];
        float n0 = g_csr_norm[j];
        float4 h0 = *(const float4*)&src[(size_t)s0 * F + f0];
        acc.x += h0.x * n0; acc.y += h0.y * n0; acc.z += h0.z * n0; acc.w += h0.w * n0;
    }
    *(float4*)&dst[(size_t)node * F + f0] = acc;

    if (DO_STATS) {
        *(float4*)&s_ps[w][lane * 4] = acc;
        *(float4*)&s_pq[w][lane * 4] = make_float4(acc.x * acc.x, acc.y * acc.y,
                                                   acc.z * acc.z, acc.w * acc.w);
        __syncthreads();
        if (t < 128) {
            float s = 0.f;
            #pragma unroll
            for (int ww = 0; ww < 8; ww++) s += s_ps[ww][t];
            atomicAdd(&g_sumf[fb + t], s);
        } else {
            int t2 = t - 128;
            float s = 0.f;
            #pragma unroll
            for (int ww = 0; ww < 8; ww++) s += s_pq[ww][t2];
            atomicAdd(&g_sqf[fb + t2], s);
        }
    }
}

// ------------------------ standalone BN stats over g_h (layer 1, F=512) ------------------------
// 200 blocks x 256 threads; block covers 250 rows; thread handles 4 feats, every 2nd row
__global__ void bn_stats512_kernel() {
    int t = threadIdx.x;
    int c = (t & 127) * 4;
    int roff = t >> 7;
    int r0 = blockIdx.x * 250;
    float4 s = make_float4(0.f, 0.f, 0.f, 0.f);
    float4 q = make_float4(0.f, 0.f, 0.f, 0.f);
    for (int r = r0 + roff; r < r0 + 250; r += 2) {
        float4 v = *(const float4*)&g_h[(size_t)r * 512 + c];
        s.x += v.x; s.y += v.y; s.z += v.z; s.w += v.w;
        q.x += v.x * v.x; q.y += v.y * v.y; q.z += v.z * v.z; q.w += v.w * v.w;
    }
    atomicAdd(&g_sumf[c + 0], s.x); atomicAdd(&g_sumf[c + 1], s.y);
    atomicAdd(&g_sumf[c + 2], s.z); atomicAdd(&g_sumf[c + 3], s.w);
    atomicAdd(&g_sqf[c + 0], q.x);  atomicAdd(&g_sqf[c + 1], q.y);
    atomicAdd(&g_sqf[c + 2], q.z);  atomicAdd(&g_sqf[c + 3], q.w);
}

// compute scale/shift, then re-zero the accumulators for the next use/replay
__global__ void bn_finalize_kernel(const float* __restrict__ gamma,
                                   const float* __restrict__ beta) {
    int f = threadIdx.x;
    double mean = (double)g_sumf[f] * (1.0 / N_NODES);
    double var  = (double)g_sqf[f] * (1.0 / N_NODES) - mean * mean;
    float scale = gamma[f] * rsqrtf((float)var + BN_EPS);
    g_scale[f] = scale;
    g_shift[f] = beta[f] - (float)mean * scale;
    g_sumf[f] = 0.f;
    g_sqf[f]  = 0.f;
}

// ------------------------ pool (fused BN3+ReLU, run-length atomics) ------------------------
__global__ void zero_pool_kernel() {
    int i = blockIdx.x * blockDim.x + threadIdx.x;
    if (i < N_GRAPHS * H3) g_pool[i] = 0.0f;
    if (i < N_GRAPHS) g_cnt[i] = 0.0f;
}

// 128 threads/block, 32 nodes/block; batch is sorted -> few graph transitions
__global__ void pool_kernel(const int* __restrict__ batch) {
    int f  = threadIdx.x;
    int n0 = blockIdx.x * 32;
    int ne = min(n0 + 32, N_NODES);
    float sc = g_scale[f], sh = g_shift[f];
    int curg = batch[n0];
    float run = 0.f, cnt = 0.f;
    for (int n = n0; n < ne; n++) {
        int g = batch[n];
        if (g != curg) {
            atomicAdd(&g_pool[curg * H3 + f], run);
            if (f == 0) atomicAdd(&g_cnt[curg], cnt);
            run = 0.f; cnt = 0.f; curg = g;
        }
        float v = g_h[(size_t)n * H3 + f];
        run += fmaxf(fmaf(v, sc, sh), 0.f);
        cnt += 1.f;
    }
    atomicAdd(&g_pool[curg * H3 + f], run);
    if (f == 0) atomicAdd(&g_cnt[curg], cnt);
}

__global__ void final_linear_kernel(const float* __restrict__ Wo,
                                    const float* __restrict__ bo,
                                    float* __restrict__ out) {
    int t = blockIdx.x * blockDim.x + threadIdx.x;
    if (t >= N_GRAPHS * N_CLS) return;
    int g = t / N_CLS;
    int c = t % N_CLS;
    float inv_cnt = 1.0f / fmaxf(g_cnt[g], 1.0f);
    float s = 0.0f;
    #pragma unroll 8
    for (int f = 0; f < H3; f++)
        s += g_pool[g * H3 + f] * Wo[f * N_CLS + c];
    out[t] = s * inv_cnt + bo[c];
}

// ------------------------ host orchestration ------------------------
extern "C" void kernel_launch(void* const* d_in, const int* in_sizes, int n_in,
                              void* d_out, int out_size) {
    const float* x     = (const float*)d_in[0];
    const int*   ei    = (const int*)d_in[1];
    const int*   batch = (const int*)d_in[2];
    const float* W1 = (const float*)d_in[3];
    const float* g1 = (const float*)d_in[5];
    const float* be1 = (const float*)d_in[6];
    const float* W2 = (const float*)d_in[7];
    const float* g2 = (const float*)d_in[9];
    const float* be2 = (const float*)d_in[10];
    const float* W3 = (const float*)d_in[11];
    const float* g3 = (const float*)d_in[13];
    const float* be3 = (const float*)d_in[14];
    const float* Wo = (const float*)d_in[15];
    const float* bo = (const float*)d_in[16];
    float* out = (float*)d_out;

    void *hp = nullptr, *aggp = nullptr;
    cudaGetSymbolAddress(&hp, g_h);
    cudaGetSymbolAddress(&aggp, g_agg);
    float* hbuf   = (float*)hp;
    float* aggbuf = (float*)aggp;

    // CSR build (by target) + dinv
    zero_counts_kernel<<<(N_NODES + 255) / 256, 256>>>();
    count_deg_kernel<<<(N_EDGES + 255) / 256, 256>>>(ei);
    finalize_dinv_kernel<<<(N_NODES + 255) / 256, 256>>>();
    partial_sum_kernel<<<SCAN_NB, 1024>>>();
    scan_bsum_kernel<<<1, 64>>>();
    offsets_kernel<<<SCAN_NB, 1024>>>();
    fill_csr_kernel<<<(N_EDGES + 255) / 256, 256>>>(ei);

    const int MB = (N_NODES + 127) / 128;   // 391

    // layer 1 (pre-aggregated: conv = (A_hat x) @ W1)
    gather_kernel<false><<<dim3(N_NODES / 8, 1), 256>>>(x, aggbuf, F_IN);
    gemm_tf32_kernel<false><<<dim3(H1 / 128, MB), 256>>>(aggbuf, W1, hbuf, N_NODES, F_IN, H1);
    bn_stats512_kernel<<<200, 256>>>();
    bn_finalize_kernel<<<1, H1>>>(g1, be1);

    // layer 2: h = relu(bn(g_h)) @ W2 (BN folded into A-load), then gather + stats
    gemm_tf32_kernel<true><<<dim3(H2 / 128, MB), 256>>>(hbuf, W2, aggbuf, N_NODES, H1, H2);
    gather_kernel<true><<<dim3(N_NODES / 8, H2 / 128), 256>>>(aggbuf, hbuf, H2);
    bn_finalize_kernel<<<1, H2>>>(g2, be2);

    // layer 3
    gemm_tf32_kernel<true><<<dim3(H3 / 128, MB), 256>>>(hbuf, W3, aggbuf, N_NODES, H2, H3);
    gather_kernel<true><<<dim3(N_NODES / 8, H3 / 128), 256>>>(aggbuf, hbuf, H3);
    bn_finalize_kernel<<<1, H3>>>(g3, be3);

    // pool (BN3+ReLU fused) + output head
    zero_pool_kernel<<<(N_GRAPHS * H3 + 255) / 256, 256>>>();
    pool_kernel<<<(N_NODES + 31) / 32, 128>>>(batch);
    final_linear_kernel<<<(N_GRAPHS * N_CLS + 255) / 256, 256>>>(Wo, bo, out);
}

// round 5
// speedup vs baseline: 4.9012x; 1.0707x over previous
#include <cuda_runtime.h>
#include <cuda_bf16.h>
#include <math.h>
#include <stdint.h>

#define N_NODES 50000
#define N_EDGES 800000
#define N_GRAPHS 64
#define F_IN 128
#define H1 512
#define H2 256
#define H3 128
#define N_CLS 10
#define BN_EPS 1e-5f
#define HMAX 512
#define SCAN_NB 49   // ceil(50000/1024)

// weight segment offsets in preconverted buffers
#define W1_OFF 0
#define W2_OFF 65536          // 128*512
#define W3_OFF 196608         // + 512*256
#define W_TOTAL 229376        // + 256*128

// ------------------------ scratch (device globals; no allocs) ------------------------
__device__ float    g_deg[N_NODES];                    // dinv
__device__ int      g_counts[N_NODES];
__device__ int      g_cur[N_NODES];
__device__ int      g_bsum[64];
__device__ int      g_bbase[64];
__device__ int      g_offs[N_NODES + 1];
__device__ int      g_csr_src[N_EDGES];
__device__ float    g_csr_norm[N_EDGES];
__device__ float    g_h  [(size_t)N_NODES * HMAX];     // fp32 scratch A
__device__ float    g_agg[(size_t)N_NODES * HMAX];     // fp32 scratch B
__device__ uint32_t g_b16[(size_t)N_NODES * 128];      // packed bf16x2 (max F=256)
__device__ uint32_t g_wh[W_TOTAL];                     // weights tf32 hi
__device__ uint32_t g_wl[W_TOTAL];                     // weights tf32 lo
__device__ float    g_sumf[HMAX];                      // zero-init; re-zeroed by bn_finalize
__device__ float    g_sqf [HMAX];
__device__ float    g_scale[HMAX];
__device__ float    g_shift[HMAX];
__device__ float    g_pool[N_GRAPHS * H3];
__device__ float    g_cnt [N_GRAPHS];

// ------------------------ helpers ------------------------
__device__ __forceinline__ uint32_t f2tf32(float f) {
    uint32_t r;
    asm("cvt.rna.tf32.f32 %0, %1;" : "=r"(r) : "f"(f));
    return r;
}

__device__ __forceinline__ float2 b2f(uint32_t u) {   // bf16x2 -> float2 (low = .x)
    return make_float2(__uint_as_float(u << 16), __uint_as_float(u & 0xFFFF0000u));
}

__device__ __forceinline__ void mma_tf32(float4& c, const uint32_t* a,
                                         uint32_t b0, uint32_t b1) {
    asm volatile(
        "mma.sync.aligned.m16n8k8.row.col.f32.tf32.tf32.f32 "
        "{%0,%1,%2,%3}, {%4,%5,%6,%7}, {%8,%9}, {%0,%1,%2,%3};"
        : "+f"(c.x), "+f"(c.y), "+f"(c.z), "+f"(c.w)
        : "r"(a[0]), "r"(a[1]), "r"(a[2]), "r"(a[3]), "r"(b0), "r"(b1));
}

// ------------------------ pre-conversions ------------------------
__global__ void conv_w_kernel(const float* __restrict__ W, uint32_t* __restrict__ wh,
                              uint32_t* __restrict__ wl, int n) {
    int i = blockIdx.x * blockDim.x + threadIdx.x;
    if (i >= n) return;
    float w = W[i];
    uint32_t h = f2tf32(w);
    wh[i] = h;
    wl[i] = f2tf32(w - __uint_as_float(h));
}

// x (50000x128 fp32) -> packed bf16x2
__global__ void conv_x_kernel(const float* __restrict__ x) {
    int i = blockIdx.x * blockDim.x + threadIdx.x;   // over float4s: 1.6M
    if (i >= N_NODES * F_IN / 4) return;
    float4 v = *(const float4*)&x[i * 4];
    __nv_bfloat162 a = __float22bfloat162_rn(make_float2(v.x, v.y));
    __nv_bfloat162 b = __float22bfloat162_rn(make_float2(v.z, v.w));
    uint2 o;
    o.x = *(uint32_t*)&a;
    o.y = *(uint32_t*)&b;
    *(uint2*)&g_b16[i * 2] = o;
}

// ------------------------ CSR construction ------------------------
__global__ void zero_counts_kernel() {
    int i = blockIdx.x * blockDim.x + threadIdx.x;
    if (i < N_NODES) { g_counts[i] = 0; g_cur[i] = 0; }
}

__global__ void count_deg_kernel(const int* __restrict__ ei) {
    int e = blockIdx.x * blockDim.x + threadIdx.x;
    if (e < N_EDGES) atomicAdd(&g_counts[ei[N_EDGES + e]], 1);
}

__global__ void finalize_dinv_kernel() {
    int i = blockIdx.x * blockDim.x + threadIdx.x;
    if (i < N_NODES) g_deg[i] = rsqrtf((float)g_counts[i] + 1.0f);
}

__global__ void partial_sum_kernel() {
    __shared__ int s[1024];
    int t = threadIdx.x;
    int i = blockIdx.x * 1024 + t;
    s[t] = (i < N_NODES) ? g_counts[i] : 0;
    __syncthreads();
    for (int st = 512; st > 0; st >>= 1) {
        if (t < st) s[t] += s[t + st];
        __syncthreads();
    }
    if (t == 0) g_bsum[blockIdx.x] = s[0];
}

__global__ void scan_bsum_kernel() {
    __shared__ int s[64];
    int t = threadIdx.x;
    int v0 = (t < SCAN_NB) ? g_bsum[t] : 0;
    s[t] = v0;
    __syncthreads();
    for (int d = 1; d < 64; d <<= 1) {
        int v = (t >= d) ? s[t - d] : 0;
        __syncthreads();
        s[t] += v;
        __syncthreads();
    }
    if (t < SCAN_NB) g_bbase[t] = s[t] - v0;   // exclusive
    if (t == 0) g_offs[N_NODES] = N_EDGES;
}

__global__ void offsets_kernel() {
    __shared__ int s[1024];
    int t = threadIdx.x;
    int i = blockIdx.x * 1024 + t;
    int c = (i < N_NODES) ? g_counts[i] : 0;
    s[t] = c;
    __syncthreads();
    for (int d = 1; d < 1024; d <<= 1) {
        int v = (t >= d) ? s[t - d] : 0;
        __syncthreads();
        s[t] += v;
        __syncthreads();
    }
    if (i < N_NODES) g_offs[i] = g_bbase[blockIdx.x] + s[t] - c;
}

__global__ void fill_csr_kernel(const int* __restrict__ ei) {
    int e = blockIdx.x * blockDim.x + threadIdx.x;
    if (e >= N_EDGES) return;
    int r = ei[e];
    int c = ei[N_EDGES + e];
    int pos = g_offs[c] + atomicAdd(&g_cur[c], 1);
    g_csr_src[pos] = r;
    g_csr_norm[pos] = g_deg[r] * g_deg[c];
}

// ------------------------ GEMM: C = f(A) @ W  (tf32 TC, preconverted W hi+lo) ------------------------
// 128x128 block, BK=8, 256 threads (8 warps: 2m x 4n, warp tile 64x32), double buffered.
#define ASTR 12   // sA row stride ([m][k]) — conflict-free fragment loads
#define BSTR 12   // sB row stride ([n][k]) — conflict-free fragment loads

template<bool APPLY_BN, bool DO_STATS, bool OUT_BF16>
__global__ void __launch_bounds__(256, 2)
gemm_tf32_kernel(const float* __restrict__ A,
                 const uint32_t* __restrict__ Bh, const uint32_t* __restrict__ Bl,
                 float* __restrict__ Cf, uint32_t* __restrict__ Cb,
                 int M, int K, int N) {
    __shared__ uint32_t sA [2][128 * ASTR];
    __shared__ uint32_t sBh[2][128 * BSTR];
    __shared__ uint32_t sBl[2][128 * BSTR];
    __shared__ float sSc[HMAX], sSh[HMAX];

    int t    = threadIdx.x;
    int lane = t & 31;
    int warp = t >> 5;
    int g    = lane >> 2;      // groupID
    int tig  = lane & 3;       // threadID_in_group
    int wm   = (warp & 1) * 64;
    int wn   = (warp >> 1) * 32;
    int bm   = blockIdx.y * 128;
    int bcn  = blockIdx.x * 128;

    if (APPLY_BN) {
        for (int i = t; i < K; i += 256) { sSc[i] = g_scale[i]; sSh[i] = g_shift[i]; }
        __syncthreads();
    }

    // loader mappings
    int am = t >> 1, ak = (t & 1) * 4;
    bool arow = (bm + am) < M;
    const float* Ap = A + (size_t)(bm + am) * K + ak;
    int bn = t & 127;                  // column within tile
    int kb0 = (t >> 7) * 4;            // k base (0 or 4)
    const uint32_t* Bhp = Bh + (size_t)kb0 * N + bcn + bn;
    const uint32_t* Blp = Bl + (size_t)kb0 * N + bcn + bn;

    float4 acc[4][4];
    #pragma unroll
    for (int i = 0; i < 4; i++)
        #pragma unroll
        for (int j = 0; j < 4; j++) acc[i][j] = make_float4(0.f, 0.f, 0.f, 0.f);

    uint4 ua;
    uint32_t bhv[4], blv[4];

    auto load_tile = [&](int k0) {
        float4 av = make_float4(0.f, 0.f, 0.f, 0.f);
        if (arow) av = *(const float4*)(Ap + k0);
        if (APPLY_BN && arow) {
            av.x = fmaxf(fmaf(av.x, sSc[k0 + ak + 0], sSh[k0 + ak + 0]), 0.f);
            av.y = fmaxf(fmaf(av.y, sSc[k0 + ak + 1], sSh[k0 + ak + 1]), 0.f);
            av.z = fmaxf(fmaf(av.z, sSc[k0 + ak + 2], sSh[k0 + ak + 2]), 0.f);
            av.w = fmaxf(fmaf(av.w, sSc[k0 + ak + 3], sSh[k0 + ak + 3]), 0.f);
        }
        ua.x = f2tf32(av.x); ua.y = f2tf32(av.y);
        ua.z = f2tf32(av.z); ua.w = f2tf32(av.w);
        #pragma unroll
        for (int i = 0; i < 4; i++) {
            bhv[i] = Bhp[(size_t)(k0 + i) * N];
            blv[i] = Blp[(size_t)(k0 + i) * N];
        }
    };

    auto store_tile = [&](int buf) {
        *(uint4*)&sA[buf][am * ASTR + ak] = ua;
        #pragma unroll
        for (int i = 0; i < 4; i++) {
            sBh[buf][bn * BSTR + kb0 + i] = bhv[i];
            sBl[buf][bn * BSTR + kb0 + i] = blv[i];
        }
    };

    load_tile(0);
    store_tile(0);
    __syncthreads();

    int buf = 0;
    for (int k0 = 0; k0 < K; k0 += 8) {
        bool more = (k0 + 8) < K;
        if (more) load_tile(k0 + 8);

        uint32_t af[4][4];
        #pragma unroll
        for (int i = 0; i < 4; i++) {
            int r0 = wm + 16 * i;
            af[i][0] = sA[buf][(r0 + g    ) * ASTR + tig    ];
            af[i][1] = sA[buf][(r0 + g + 8) * ASTR + tig    ];
            af[i][2] = sA[buf][(r0 + g    ) * ASTR + tig + 4];
            af[i][3] = sA[buf][(r0 + g + 8) * ASTR + tig + 4];
        }
        #pragma unroll
        for (int j = 0; j < 4; j++) {
            int nb = wn + 8 * j + g;
            uint32_t bh0 = sBh[buf][nb * BSTR + tig    ];
            uint32_t bh1 = sBh[buf][nb * BSTR + tig + 4];
            uint32_t bl0 = sBl[buf][nb * BSTR + tig    ];
            uint32_t bl1 = sBl[buf][nb * BSTR + tig + 4];
            #pragma unroll
            for (int i = 0; i < 4; i++) {
                mma_tf32(acc[i][j], af[i], bh0, bh1);
                mma_tf32(acc[i][j], af[i], bl0, bl1);
            }
        }

        if (more) store_tile(buf ^ 1);
        __syncthreads();
        buf ^= 1;
    }

    // fused BN stats (layer-1): OOB rows have acc==0 so add unconditionally
    if (DO_STATS) {
        #pragma unroll
        for (int j = 0; j < 4; j++) {
            float sx = 0.f, sy = 0.f, qx = 0.f, qy = 0.f;
            #pragma unroll
            for (int i = 0; i < 4; i++) {
                sx += acc[i][j].x + acc[i][j].z;
                sy += acc[i][j].y + acc[i][j].w;
                qx += acc[i][j].x * acc[i][j].x + acc[i][j].z * acc[i][j].z;
                qy += acc[i][j].y * acc[i][j].y + acc[i][j].w * acc[i][j].w;
            }
            #pragma unroll
            for (int m = 4; m < 32; m <<= 1) {
                sx += __shfl_xor_sync(0xffffffffu, sx, m);
                sy += __shfl_xor_sync(0xffffffffu, sy, m);
                qx += __shfl_xor_sync(0xffffffffu, qx, m);
                qy += __shfl_xor_sync(0xffffffffu, qy, m);
            }
            if (lane < 4) {
                int n = bcn + wn + 8 * j + 2 * lane;
                atomicAdd(&g_sumf[n],     sx);
                atomicAdd(&g_sumf[n + 1], sy);
                atomicAdd(&g_sqf [n],     qx);
                atomicAdd(&g_sqf [n + 1], qy);
            }
        }
    }

    // epilogue
    #pragma unroll
    for (int i = 0; i < 4; i++) {
        int m0 = bm + wm + 16 * i + g;
        int m1 = m0 + 8;
        #pragma unroll
        for (int j = 0; j < 4; j++) {
            int n = bcn + wn + 8 * j + 2 * tig;
            if (OUT_BF16) {
                if (m0 < M)
                    ((__nv_bfloat162*)Cb)[((size_t)m0 * N + n) >> 1] =
                        __float22bfloat162_rn(make_float2(acc[i][j].x, acc[i][j].y));
                if (m1 < M)
                    ((__nv_bfloat162*)Cb)[((size_t)m1 * N + n) >> 1] =
                        __float22bfloat162_rn(make_float2(acc[i][j].z, acc[i][j].w));
            } else {
                if (m0 < M) *(float2*)&Cf[(size_t)m0 * N + n] = make_float2(acc[i][j].x, acc[i][j].y);
                if (m1 < M) *(float2*)&Cf[(size_t)m1 * N + n] = make_float2(acc[i][j].z, acc[i][j].w);
            }
        }
    }
}

// ------------------------ CSR gather over bf16 rows (+ optional fused BN stats) ------------------------
// one warp per (node, 128-feature chunk); grid=(6250, F/128), block=256 (8 nodes)
template<bool DO_STATS>
__global__ void gather_bf16_kernel(const uint32_t* __restrict__ src,
                                   float* __restrict__ dst, int F) {
    __shared__ float s_ps[8][128];
    __shared__ float s_pq[8][128];

    int t    = threadIdx.x;
    int lane = t & 31;
    int w    = t >> 5;
    int node = blockIdx.x * 8 + w;          // 50000 = 6250*8
    int fb   = blockIdx.y << 7;
    int f0   = fb + lane * 4;
    int Fu   = F >> 1;                       // row pitch in uint32
    int f0u  = (f0 >> 1);                    // uint offset

    float di = g_deg[node];
    float sl = di * di;
    uint2 sv = *(const uint2*)&src[(size_t)node * Fu + f0u];
    float2 sa = b2f(sv.x), sb = b2f(sv.y);
    float4 acc = make_float4(sa.x * sl, sa.y * sl, sb.x * sl, sb.y * sl);

    int j   = g_offs[node];
    int end = g_offs[node + 1];
    for (; j + 1 < end; j += 2) {
        int   s0 = g_csr_src[j];
        int   s1 = g_csr_src[j + 1];
        float n0 = g_csr_norm[j];
        float n1 = g_csr_norm[j + 1];
        uint2 u0 = *(const uint2*)&src[(size_t)s0 * Fu + f0u];
        uint2 u1 = *(const uint2*)&src[(size_t)s1 * Fu + f0u];
        float2 a0 = b2f(u0.x), b0 = b2f(u0.y);
        float2 a1 = b2f(u1.x), b1 = b2f(u1.y);
        acc.x = fmaf(a0.x, n0, acc.x); acc.y = fmaf(a0.y, n0, acc.y);
        acc.z = fmaf(b0.x, n0, acc.z); acc.w = fmaf(b0.y, n0, acc.w);
        acc.x = fmaf(a1.x, n1, acc.x); acc.y = fmaf(a1.y, n1, acc.y);
        acc.z = fmaf(b1.x, n1, acc.z); acc.w = fmaf(b1.y, n1, acc.w);
    }
    if (j < end) {
        int   s0 = g_csr_src[j];
        float n0 = g_csr_norm[j];
        uint2 u0 = *(const uint2*)&src[(size_t)s0 * Fu + f0u];
        float2 a0 = b2f(u0.x), b0 = b2f(u0.y);
        acc.x = fmaf(a0.x, n0, acc.x); acc.y = fmaf(a0.y, n0, acc.y);
        acc.z = fmaf(b0.x, n0, acc.z); acc.w = fmaf(b0.y, n0, acc.w);
    }
    *(float4*)&dst[(size_t)node * F + f0] = acc;

    if (DO_STATS) {
        *(float4*)&s_ps[w][lane * 4] = acc;
        *(float4*)&s_pq[w][lane * 4] = make_float4(acc.x * acc.x, acc.y * acc.y,
                                                   acc.z * acc.z, acc.w * acc.w);
        __syncthreads();
        if (t < 128) {
            float s = 0.f;
            #pragma unroll
            for (int ww = 0; ww < 8; ww++) s += s_ps[ww][t];
            atomicAdd(&g_sumf[fb + t], s);
        } else {
            int t2 = t - 128;
            float s = 0.f;
            #pragma unroll
            for (int ww = 0; ww < 8; ww++) s += s_pq[ww][t2];
            atomicAdd(&g_sqf[fb + t2], s);
        }
    }
}

// compute scale/shift, then re-zero the accumulators for the next use/replay
__global__ void bn_finalize_kernel(const float* __restrict__ gamma,
                                   const float* __restrict__ beta) {
    int f = threadIdx.x;
    double mean = (double)g_sumf[f] * (1.0 / N_NODES);
    double var  = (double)g_sqf[f] * (1.0 / N_NODES) - mean * mean;
    float scale = gamma[f] * rsqrtf((float)var + BN_EPS);
    g_scale[f] = scale;
    g_shift[f] = beta[f] - (float)mean * scale;
    g_sumf[f] = 0.f;
    g_sqf[f]  = 0.f;
}

// ------------------------ pool (fused BN3+ReLU, run-length atomics) ------------------------
__global__ void zero_pool_kernel() {
    int i = blockIdx.x * blockDim.x + threadIdx.x;
    if (i < N_GRAPHS * H3) g_pool[i] = 0.0f;
    if (i < N_GRAPHS) g_cnt[i] = 0.0f;
}

// 128 threads/block, 32 nodes/block; batch is sorted -> few graph transitions
__global__ void pool_kernel(const int* __restrict__ batch) {
    int f  = threadIdx.x;
    int n0 = blockIdx.x * 32;
    int ne = min(n0 + 32, N_NODES);
    float sc = g_scale[f], sh = g_shift[f];
    int curg = batch[n0];
    float run = 0.f, cnt = 0.f;
    for (int n = n0; n < ne; n++) {
        int g = batch[n];
        if (g != curg) {
            atomicAdd(&g_pool[curg * H3 + f], run);
            if (f == 0) atomicAdd(&g_cnt[curg], cnt);
            run = 0.f; cnt = 0.f; curg = g;
        }
        float v = g_h[(size_t)n * H3 + f];
        run += fmaxf(fmaf(v, sc, sh), 0.f);
        cnt += 1.f;
    }
    atomicAdd(&g_pool[curg * H3 + f], run);
    if (f == 0) atomicAdd(&g_cnt[curg], cnt);
}

__global__ void final_linear_kernel(const float* __restrict__ Wo,
                                    const float* __restrict__ bo,
                                    float* __restrict__ out) {
    int t = blockIdx.x * blockDim.x + threadIdx.x;
    if (t >= N_GRAPHS * N_CLS) return;
    int g = t / N_CLS;
    int c = t % N_CLS;
    float inv_cnt = 1.0f / fmaxf(g_cnt[g], 1.0f);
    float s = 0.0f;
    #pragma unroll 8
    for (int f = 0; f < H3; f++)
        s += g_pool[g * H3 + f] * Wo[f * N_CLS + c];
    out[t] = s * inv_cnt + bo[c];
}

// ------------------------ host orchestration ------------------------
extern "C" void kernel_launch(void* const* d_in, const int* in_sizes, int n_in,
                              void* d_out, int out_size) {
    const float* x     = (const float*)d_in[0];
    const int*   ei    = (const int*)d_in[1];
    const int*   batch = (const int*)d_in[2];
    const float* W1 = (const float*)d_in[3];
    const float* g1 = (const float*)d_in[5];
    const float* be1 = (const float*)d_in[6];
    const float* W2 = (const float*)d_in[7];
    const float* g2 = (const float*)d_in[9];
    const float* be2 = (const float*)d_in[10];
    const float* W3 = (const float*)d_in[11];
    const float* g3 = (const float*)d_in[13];
    const float* be3 = (const float*)d_in[14];
    const float* Wo = (const float*)d_in[15];
    const float* bo = (const float*)d_in[16];
    float* out = (float*)d_out;

    void *hp = nullptr, *aggp = nullptr, *b16p = nullptr, *whp = nullptr, *wlp = nullptr;
    cudaGetSymbolAddress(&hp, g_h);
    cudaGetSymbolAddress(&aggp, g_agg);
    cudaGetSymbolAddress(&b16p, g_b16);
    cudaGetSymbolAddress(&whp, g_wh);
    cudaGetSymbolAddress(&wlp, g_wl);
    float*    hbuf   = (float*)hp;
    float*    aggbuf = (float*)aggp;
    uint32_t* b16    = (uint32_t*)b16p;
    uint32_t* wh     = (uint32_t*)whp;
    uint32_t* wl     = (uint32_t*)wlp;

    // pre-conversions (independent of CSR)
    conv_x_kernel<<<(N_NODES * F_IN / 4 + 255) / 256, 256>>>(x);
    conv_w_kernel<<<(65536 + 255) / 256, 256>>>(W1, wh + W1_OFF, wl + W1_OFF, 65536);
    conv_w_kernel<<<(131072 + 255) / 256, 256>>>(W2, wh + W2_OFF, wl + W2_OFF, 131072);
    conv_w_kernel<<<(32768 + 255) / 256, 256>>>(W3, wh + W3_OFF, wl + W3_OFF, 32768);

    // CSR build (by target) + dinv
    zero_counts_kernel<<<(N_NODES + 255) / 256, 256>>>();
    count_deg_kernel<<<(N_EDGES + 255) / 256, 256>>>(ei);
    finalize_dinv_kernel<<<(N_NODES + 255) / 256, 256>>>();
    partial_sum_kernel<<<SCAN_NB, 1024>>>();
    scan_bsum_kernel<<<1, 64>>>();
    offsets_kernel<<<SCAN_NB, 1024>>>();
    fill_csr_kernel<<<(N_EDGES + 255) / 256, 256>>>(ei);

    const int MB = (N_NODES + 127) / 128;   // 391

    // layer 1: aggX = A_hat x (bf16 msgs) ; h1 = aggX @ W1 (fp32 out, fused stats)
    gather_bf16_kernel<false><<<dim3(N_NODES / 8, 1), 256>>>(b16, aggbuf, F_IN);
    gemm_tf32_kernel<false, true, false><<<dim3(H1 / 128, MB), 256>>>(
        aggbuf, wh + W1_OFF, wl + W1_OFF, hbuf, nullptr, N_NODES, F_IN, H1);
    bn_finalize_kernel<<<1, H1>>>(g1, be1);

    // layer 2: h2 = relu(bn(h1)) @ W2 (bf16 out) ; agg2 = A_hat h2 (+stats)
    gemm_tf32_kernel<true, false, true><<<dim3(H2 / 128, MB), 256>>>(
        hbuf, wh + W2_OFF, wl + W2_OFF, nullptr, b16, N_NODES, H1, H2);
    gather_bf16_kernel<true><<<dim3(N_NODES / 8, H2 / 128), 256>>>(b16, aggbuf, H2);
    bn_finalize_kernel<<<1, H2>>>(g2, be2);

    // layer 3: h3 = relu(bn(agg2)) @ W3 (bf16 out) ; agg3 = A_hat h3 (+stats) -> g_h
    gemm_tf32_kernel<true, false, true><<<dim3(H3 / 128, MB), 256>>>(
        aggbuf, wh + W3_OFF, wl + W3_OFF, nullptr, b16, N_NODES, H2, H3);
    gather_bf16_kernel<true><<<dim3(N_NODES / 8, 1), 256>>>(b16, hbuf, H3);
    bn_finalize_kernel<<<1, H3>>>(g3, be3);

    // pool (BN3+ReLU fused) + output head
    zero_pool_kernel<<<(N_GRAPHS * H3 + 255) / 256, 256>>>();
    pool_kernel<<<(N_NODES + 31) / 32, 128>>>(batch);
    final_linear_kernel<<<(N_GRAPHS * N_CLS + 255) / 256, 256>>>(Wo, bo, out);
}

// round 6
// speedup vs baseline: 6.3847x; 1.3027x over previous
#include <cuda_runtime.h>
#include <cuda_bf16.h>
#include <math.h>
#include <stdint.h>

#define N_NODES 50000
#define N_EDGES 800000
#define N_GRAPHS 64
#define F_IN 128
#define H1 512
#define H2 256
#define H3 128
#define N_CLS 10
#define BN_EPS 1e-5f
#define HMAX 512
#define SCAN_NB 49   // ceil(50000/1024)

// packed-weight segment offsets ([N][K/2] uint32 layout)
#define W1P_OFF 0
#define W2P_OFF 32768          // 512*64
#define W3P_OFF 98304          // + 256*256
#define WP_TOTAL 114688        // + 128*128

// ------------------------ scratch (device globals; no allocs) ------------------------
__device__ float    g_deg[N_NODES];                    // dinv
__device__ int      g_counts[N_NODES];
__device__ int      g_cur[N_NODES];
__device__ int      g_bsum[64];
__device__ int      g_bbase[64];
__device__ int      g_offs[N_NODES + 1];
__device__ int      g_csr_src[N_EDGES];
__device__ float    g_csr_norm[N_EDGES];
__device__ float    g_h  [(size_t)N_NODES * HMAX];     // fp32 scratch A
__device__ float    g_agg[(size_t)N_NODES * HMAX];     // fp32 scratch B
__device__ uint32_t g_b16[(size_t)N_NODES * 128];      // packed bf16x2 (max F=256)
__device__ uint32_t g_wbh[WP_TOTAL];                   // weights bf16-hi packed x2
__device__ uint32_t g_wbl[WP_TOTAL];                   // weights bf16-lo packed x2
__device__ float    g_sumf[HMAX];                      // zero-init; re-zeroed by bn_finalize
__device__ float    g_sqf [HMAX];
__device__ float    g_scale[HMAX];
__device__ float    g_shift[HMAX];
__device__ float    g_pool[N_GRAPHS * H3];
__device__ float    g_cnt [N_GRAPHS];

// ------------------------ helpers ------------------------
__device__ __forceinline__ float2 b2f(uint32_t u) {   // bf16x2 -> float2 (low = .x)
    return make_float2(__uint_as_float(u << 16), __uint_as_float(u & 0xFFFF0000u));
}

__device__ __forceinline__ uint32_t f2b2(float x, float y) {  // pack (x=low, y=high)
    __nv_bfloat162 h = __float22bfloat162_rn(make_float2(x, y));
    return *(uint32_t*)&h;
}

__device__ __forceinline__ void mma_bf16(float4& c, uint32_t a0, uint32_t a1,
                                         uint32_t a2, uint32_t a3,
                                         uint32_t b0, uint32_t b1) {
    asm volatile(
        "mma.sync.aligned.m16n8k16.row.col.f32.bf16.bf16.f32 "
        "{%0,%1,%2,%3}, {%4,%5,%6,%7}, {%8,%9}, {%0,%1,%2,%3};"
        : "+f"(c.x), "+f"(c.y), "+f"(c.z), "+f"(c.w)
        : "r"(a0), "r"(a1), "r"(a2), "r"(a3), "r"(b0), "r"(b1));
}

// ------------------------ pre-conversions ------------------------
// W [K][N] fp32 -> packed bf16 hi/lo, [N][K/2] uint32 (pair = k even/odd)
__global__ void conv_wp_kernel(const float* __restrict__ W, uint32_t* __restrict__ wh,
                               uint32_t* __restrict__ wl, int K, int N) {
    int idx = blockIdx.x * blockDim.x + threadIdx.x;
    int Kp = K >> 1;
    if (idx >= N * Kp) return;
    int n = idx / Kp, kp = idx - n * Kp;
    float w0 = W[(size_t)(2 * kp)     * N + n];
    float w1 = W[(size_t)(2 * kp + 1) * N + n];
    __nv_bfloat16 h0 = __float2bfloat16(w0);
    __nv_bfloat16 h1 = __float2bfloat16(w1);
    float l0 = w0 - __bfloat162float(h0);
    float l1 = w1 - __bfloat162float(h1);
    __nv_bfloat162 ph; ph.x = h0; ph.y = h1;
    wh[idx] = *(uint32_t*)&ph;
    wl[idx] = f2b2(l0, l1);
}

// x (50000x128 fp32) -> packed bf16x2
__global__ void conv_x_kernel(const float* __restrict__ x) {
    int i = blockIdx.x * blockDim.x + threadIdx.x;
    if (i >= N_NODES * F_IN / 4) return;
    float4 v = *(const float4*)&x[i * 4];
    uint2 o;
    o.x = f2b2(v.x, v.y);
    o.y = f2b2(v.z, v.w);
    *(uint2*)&g_b16[i * 2] = o;
}

// ------------------------ CSR construction ------------------------
__global__ void zero_counts_kernel() {
    int i = blockIdx.x * blockDim.x + threadIdx.x;
    if (i < N_NODES) { g_counts[i] = 0; g_cur[i] = 0; }
}

__global__ void count_deg_kernel(const int* __restrict__ ei) {
    int e = blockIdx.x * blockDim.x + threadIdx.x;
    if (e < N_EDGES) atomicAdd(&g_counts[ei[N_EDGES + e]], 1);
}

__global__ void finalize_dinv_kernel() {
    int i = blockIdx.x * blockDim.x + threadIdx.x;
    if (i < N_NODES) g_deg[i] = rsqrtf((float)g_counts[i] + 1.0f);
}

__global__ void partial_sum_kernel() {
    __shared__ int s[1024];
    int t = threadIdx.x;
    int i = blockIdx.x * 1024 + t;
    s[t] = (i < N_NODES) ? g_counts[i] : 0;
    __syncthreads();
    for (int st = 512; st > 0; st >>= 1) {
        if (t < st) s[t] += s[t + st];
        __syncthreads();
    }
    if (t == 0) g_bsum[blockIdx.x] = s[0];
}

__global__ void scan_bsum_kernel() {
    __shared__ int s[64];
    int t = threadIdx.x;
    int v0 = (t < SCAN_NB) ? g_bsum[t] : 0;
    s[t] = v0;
    __syncthreads();
    for (int d = 1; d < 64; d <<= 1) {
        int v = (t >= d) ? s[t - d] : 0;
        __syncthreads();
        s[t] += v;
        __syncthreads();
    }
    if (t < SCAN_NB) g_bbase[t] = s[t] - v0;   // exclusive
    if (t == 0) g_offs[N_NODES] = N_EDGES;
}

__global__ void offsets_kernel() {
    __shared__ int s[1024];
    int t = threadIdx.x;
    int i = blockIdx.x * 1024 + t;
    int c = (i < N_NODES) ? g_counts[i] : 0;
    s[t] = c;
    __syncthreads();
    for (int d = 1; d < 1024; d <<= 1) {
        int v = (t >= d) ? s[t - d] : 0;
        __syncthreads();
        s[t] += v;
        __syncthreads();
    }
    if (i < N_NODES) g_offs[i] = g_bbase[blockIdx.x] + s[t] - c;
}

__global__ void fill_csr_kernel(const int* __restrict__ ei) {
    int e = blockIdx.x * blockDim.x + threadIdx.x;
    if (e >= N_EDGES) return;
    int r = ei[e];
    int c = ei[N_EDGES + e];
    int pos = g_offs[c] + atomicAdd(&g_cur[c], 1);
    g_csr_src[pos] = r;
    g_csr_norm[pos] = g_deg[r] * g_deg[c];
}

// ------------------------ GEMM: C = f(A) @ W  (bf16 TC, W hi+lo, A bf16) ------------------------
// 128x128 block, BK=16, 256 threads (8 warps: 2m x 4n, warp tile 64x32), double buffered.
// smem rows hold 8 packed uint32 (16 bf16) + pad to stride 12 (conflict-free fragments).
#define PSTR 12

template<bool APPLY_BN, bool DO_STATS, bool OUT_BF16>
__global__ void __launch_bounds__(256, 2)
gemm_bf16_kernel(const float* __restrict__ A,
                 const uint32_t* __restrict__ Bh, const uint32_t* __restrict__ Bl,
                 float* __restrict__ Cf, uint32_t* __restrict__ Cb,
                 int M, int K, int N) {
    __shared__ uint32_t sA [2][128 * PSTR];
    __shared__ uint32_t sBh[2][128 * PSTR];
    __shared__ uint32_t sBl[2][128 * PSTR];
    __shared__ float sSc[HMAX], sSh[HMAX];

    int t    = threadIdx.x;
    int lane = t & 31;
    int warp = t >> 5;
    int g    = lane >> 2;      // groupID
    int tig  = lane & 3;       // threadID_in_group
    int wm   = (warp & 1) * 64;
    int wn   = (warp >> 1) * 32;
    int bm   = blockIdx.y * 128;
    int bcn  = blockIdx.x * 128;
    int Kp   = K >> 1;

    if (APPLY_BN) {
        for (int i = t; i < K; i += 256) { sSc[i] = g_scale[i]; sSh[i] = g_shift[i]; }
        __syncthreads();
    }

    // loader mappings: A rows (fp32), W rows ([N][K/2] packed)
    int am = t >> 1, ak = (t & 1) * 8;      // fp32 col base
    bool arow = (bm + am) < M;
    const float* Ap = A + (size_t)(bm + am) * K + ak;
    int bnr = t >> 1, bq = (t & 1) * 4;     // k-pair base
    const uint32_t* Bhp = Bh + (size_t)(bcn + bnr) * Kp + bq;
    const uint32_t* Blp = Bl + (size_t)(bcn + bnr) * Kp + bq;

    float4 acc[4][4];
    #pragma unroll
    for (int i = 0; i < 4; i++)
        #pragma unroll
        for (int j = 0; j < 4; j++) acc[i][j] = make_float4(0.f, 0.f, 0.f, 0.f);

    uint4 ua, ubh, ubl;

    auto load_tile = [&](int k0) {
        float4 a0 = make_float4(0.f, 0.f, 0.f, 0.f);
        float4 a1 = make_float4(0.f, 0.f, 0.f, 0.f);
        if (arow) {
            a0 = *(const float4*)(Ap + k0);
            a1 = *(const float4*)(Ap + k0 + 4);
        }
        if (APPLY_BN && arow) {
            int kb = k0 + ak;
            a0.x = fmaxf(fmaf(a0.x, sSc[kb + 0], sSh[kb + 0]), 0.f);
            a0.y = fmaxf(fmaf(a0.y, sSc[kb + 1], sSh[kb + 1]), 0.f);
            a0.z = fmaxf(fmaf(a0.z, sSc[kb + 2], sSh[kb + 2]), 0.f);
            a0.w = fmaxf(fmaf(a0.w, sSc[kb + 3], sSh[kb + 3]), 0.f);
            a1.x = fmaxf(fmaf(a1.x, sSc[kb + 4], sSh[kb + 4]), 0.f);
            a1.y = fmaxf(fmaf(a1.y, sSc[kb + 5], sSh[kb + 5]), 0.f);
            a1.z = fmaxf(fmaf(a1.z, sSc[kb + 6], sSh[kb + 6]), 0.f);
            a1.w = fmaxf(fmaf(a1.w, sSc[kb + 7], sSh[kb + 7]), 0.f);
        }
        ua.x = f2b2(a0.x, a0.y); ua.y = f2b2(a0.z, a0.w);
        ua.z = f2b2(a1.x, a1.y); ua.w = f2b2(a1.z, a1.w);
        ubh = *(const uint4*)(Bhp + (k0 >> 1));
        ubl = *(const uint4*)(Blp + (k0 >> 1));
    };

    auto store_tile = [&](int buf) {
        *(uint4*)&sA [buf][am  * PSTR + (t & 1) * 4] = ua;
        *(uint4*)&sBh[buf][bnr * PSTR + bq]          = ubh;
        *(uint4*)&sBl[buf][bnr * PSTR + bq]          = ubl;
    };

    load_tile(0);
    store_tile(0);
    __syncthreads();

    int buf = 0;
    for (int k0 = 0; k0 < K; k0 += 16) {
        bool more = (k0 + 16) < K;
        if (more) load_tile(k0 + 16);

        uint32_t af[4][4];
        #pragma unroll
        for (int i = 0; i < 4; i++) {
            int r0 = wm + 16 * i + g;
            af[i][0] = sA[buf][ r0      * PSTR + tig    ];
            af[i][1] = sA[buf][(r0 + 8) * PSTR + tig    ];
            af[i][2] = sA[buf][ r0      * PSTR + tig + 4];
            af[i][3] = sA[buf][(r0 + 8) * PSTR + tig + 4];
        }
        #pragma unroll
        for (int j = 0; j < 4; j++) {
            int nb = wn + 8 * j + g;
            uint32_t bh0 = sBh[buf][nb * PSTR + tig    ];
            uint32_t bh1 = sBh[buf][nb * PSTR + tig + 4];
            uint32_t bl0 = sBl[buf][nb * PSTR + tig    ];
            uint32_t bl1 = sBl[buf][nb * PSTR + tig + 4];
            #pragma unroll
            for (int i = 0; i < 4; i++) {
                mma_bf16(acc[i][j], af[i][0], af[i][1], af[i][2], af[i][3], bh0, bh1);
                mma_bf16(acc[i][j], af[i][0], af[i][1], af[i][2], af[i][3], bl0, bl1);
            }
        }

        if (more) store_tile(buf ^ 1);
        __syncthreads();
        buf ^= 1;
    }

    // fused BN stats (layer-1): OOB rows have acc==0 so add unconditionally
    if (DO_STATS) {
        #pragma unroll
        for (int j = 0; j < 4; j++) {
            float sx = 0.f, sy = 0.f, qx = 0.f, qy = 0.f;
            #pragma unroll
            for (int i = 0; i < 4; i++) {
                sx += acc[i][j].x + acc[i][j].z;
                sy += acc[i][j].y + acc[i][j].w;
                qx += acc[i][j].x * acc[i][j].x + acc[i][j].z * acc[i][j].z;
                qy += acc[i][j].y * acc[i][j].y + acc[i][j].w * acc[i][j].w;
            }
            #pragma unroll
            for (int m = 4; m < 32; m <<= 1) {
                sx += __shfl_xor_sync(0xffffffffu, sx, m);
                sy += __shfl_xor_sync(0xffffffffu, sy, m);
                qx += __shfl_xor_sync(0xffffffffu, qx, m);
                qy += __shfl_xor_sync(0xffffffffu, qy, m);
            }
            if (lane < 4) {
                int n = bcn + wn + 8 * j + 2 * lane;
                atomicAdd(&g_sumf[n],     sx);
                atomicAdd(&g_sumf[n + 1], sy);
                atomicAdd(&g_sqf [n],     qx);
                atomicAdd(&g_sqf [n + 1], qy);
            }
        }
    }

    // epilogue
    #pragma unroll
    for (int i = 0; i < 4; i++) {
        int m0 = bm + wm + 16 * i + g;
        int m1 = m0 + 8;
        #pragma unroll
        for (int j = 0; j < 4; j++) {
            int n = bcn + wn + 8 * j + 2 * tig;
            if (OUT_BF16) {
                if (m0 < M) Cb[((size_t)m0 * N + n) >> 1] = f2b2(acc[i][j].x, acc[i][j].y);
                if (m1 < M) Cb[((size_t)m1 * N + n) >> 1] = f2b2(acc[i][j].z, acc[i][j].w);
            } else {
                if (m0 < M) *(float2*)&Cf[(size_t)m0 * N + n] = make_float2(acc[i][j].x, acc[i][j].y);
                if (m1 < M) *(float2*)&Cf[(size_t)m1 * N + n] = make_float2(acc[i][j].z, acc[i][j].w);
            }
        }
    }
}

// ------------------------ CSR gather over bf16 rows (+ optional fused BN stats) ------------------------
// one warp per (node, 128-feature chunk); grid=(6250, F/128), block=256 (8 nodes)
template<bool DO_STATS>
__global__ void gather_bf16_kernel(const uint32_t* __restrict__ src,
                                   float* __restrict__ dst, int F) {
    __shared__ float s_ps[8][128];
    __shared__ float s_pq[8][128];

    int t    = threadIdx.x;
    int lane = t & 31;
    int w    = t >> 5;
    int node = blockIdx.x * 8 + w;          // 50000 = 6250*8
    int fb   = blockIdx.y << 7;
    int f0   = fb + lane * 4;
    int Fu   = F >> 1;                       // row pitch in uint32
    int f0u  = (f0 >> 1);

    float di = g_deg[node];
    float sl = di * di;
    uint2 sv = *(const uint2*)&src[(size_t)node * Fu + f0u];
    float2 sa = b2f(sv.x), sb = b2f(sv.y);
    float4 acc = make_float4(sa.x * sl, sa.y * sl, sb.x * sl, sb.y * sl);

    int j   = g_offs[node];
    int end = g_offs[node + 1];
    // unroll-4: prefetch 4 edge records, issue 4 row loads together (MLP=4)
    for (; j + 4 <= end; j += 4) {
        int   s0 = g_csr_src[j],      s1 = g_csr_src[j + 1];
        int   s2 = g_csr_src[j + 2],  s3 = g_csr_src[j + 3];
        float n0 = g_csr_norm[j],     n1 = g_csr_norm[j + 1];
        float n2 = g_csr_norm[j + 2], n3 = g_csr_norm[j + 3];
        uint2 u0 = *(const uint2*)&src[(size_t)s0 * Fu + f0u];
        uint2 u1 = *(const uint2*)&src[(size_t)s1 * Fu + f0u];
        uint2 u2 = *(const uint2*)&src[(size_t)s2 * Fu + f0u];
        uint2 u3 = *(const uint2*)&src[(size_t)s3 * Fu + f0u];
        float2 a0 = b2f(u0.x), b0 = b2f(u0.y);
        float2 a1 = b2f(u1.x), b1 = b2f(u1.y);
        float2 a2 = b2f(u2.x), b2 = b2f(u2.y);
        float2 a3 = b2f(u3.x), b3 = b2f(u3.y);
        acc.x = fmaf(a0.x, n0, acc.x); acc.y = fmaf(a0.y, n0, acc.y);
        acc.z = fmaf(b0.x, n0, acc.z); acc.w = fmaf(b0.y, n0, acc.w);
        acc.x = fmaf(a1.x, n1, acc.x); acc.y = fmaf(a1.y, n1, acc.y);
        acc.z = fmaf(b1.x, n1, acc.z); acc.w = fmaf(b1.y, n1, acc.w);
        acc.x = fmaf(a2.x, n2, acc.x); acc.y = fmaf(a2.y, n2, acc.y);
        acc.z = fmaf(b2.x, n2, acc.z); acc.w = fmaf(b2.y, n2, acc.w);
        acc.x = fmaf(a3.x, n3, acc.x); acc.y = fmaf(a3.y, n3, acc.y);
        acc.z = fmaf(b3.x, n3, acc.z); acc.w = fmaf(b3.y, n3, acc.w);
    }
    for (; j < end; j++) {
        int   s0 = g_csr_src[j];
        float n0 = g_csr_norm[j];
        uint2 u0 = *(const uint2*)&src[(size_t)s0 * Fu + f0u];
        float2 a0 = b2f(u0.x), b0 = b2f(u0.y);
        acc.x = fmaf(a0.x, n0, acc.x); acc.y = fmaf(a0.y, n0, acc.y);
        acc.z = fmaf(b0.x, n0, acc.z); acc.w = fmaf(b0.y, n0, acc.w);
    }
    *(float4*)&dst[(size_t)node * F + f0] = acc;

    if (DO_STATS) {
        *(float4*)&s_ps[w][lane * 4] = acc;
        *(float4*)&s_pq[w][lane * 4] = make_float4(acc.x * acc.x, acc.y * acc.y,
                                                   acc.z * acc.z, acc.w * acc.w);
        __syncthreads();
        if (t < 128) {
            float s = 0.f;
            #pragma unroll
            for (int ww = 0; ww < 8; ww++) s += s_ps[ww][t];
            atomicAdd(&g_sumf[fb + t], s);
        } else {
            int t2 = t - 128;
            float s = 0.f;
            #pragma unroll
            for (int ww = 0; ww < 8; ww++) s += s_pq[ww][t2];
            atomicAdd(&g_sqf[fb + t2], s);
        }
    }
}

// compute scale/shift, then re-zero the accumulators for the next use/replay
__global__ void bn_finalize_kernel(const float* __restrict__ gamma,
                                   const float* __restrict__ beta) {
    int f = threadIdx.x;
    double mean = (double)g_sumf[f] * (1.0 / N_NODES);
    double var  = (double)g_sqf[f] * (1.0 / N_NODES) - mean * mean;
    float scale = gamma[f] * rsqrtf((float)var + BN_EPS);
    g_scale[f] = scale;
    g_shift[f] = beta[f] - (float)mean * scale;
    g_sumf[f] = 0.f;
    g_sqf[f]  = 0.f;
}

// ------------------------ pool (fused BN3+ReLU, run-length atomics) ------------------------
__global__ void zero_pool_kernel() {
    int i = blockIdx.x * blockDim.x + threadIdx.x;
    if (i < N_GRAPHS * H3) g_pool[i] = 0.0f;
    if (i < N_GRAPHS) g_cnt[i] = 0.0f;
}

// 128 threads/block, 32 nodes/block; batch is sorted -> few graph transitions
__global__ void pool_kernel(const int* __restrict__ batch) {
    int f  = threadIdx.x;
    int n0 = blockIdx.x * 32;
    int ne = min(n0 + 32, N_NODES);
    float sc = g_scale[f], sh = g_shift[f];
    int curg = batch[n0];
    float run = 0.f, cnt = 0.f;
    for (int n = n0; n < ne; n++) {
        int g = batch[n];
        if (g != curg) {
            atomicAdd(&g_pool[curg * H3 + f], run);
            if (f == 0) atomicAdd(&g_cnt[curg], cnt);
            run = 0.f; cnt = 0.f; curg = g;
        }
        float v = g_h[(size_t)n * H3 + f];
        run += fmaxf(fmaf(v, sc, sh), 0.f);
        cnt += 1.f;
    }
    atomicAdd(&g_pool[curg * H3 + f], run);
    if (f == 0) atomicAdd(&g_cnt[curg], cnt);
}

__global__ void final_linear_kernel(const float* __restrict__ Wo,
                                    const float* __restrict__ bo,
                                    float* __restrict__ out) {
    int t = blockIdx.x * blockDim.x + threadIdx.x;
    if (t >= N_GRAPHS * N_CLS) return;
    int g = t / N_CLS;
    int c = t % N_CLS;
    float inv_cnt = 1.0f / fmaxf(g_cnt[g], 1.0f);
    float s = 0.0f;
    #pragma unroll 8
    for (int f = 0; f < H3; f++)
        s += g_pool[g * H3 + f] * Wo[f * N_CLS + c];
    out[t] = s * inv_cnt + bo[c];
}

// ------------------------ host orchestration ------------------------
extern "C" void kernel_launch(void* const* d_in, const int* in_sizes, int n_in,
                              void* d_out, int out_size) {
    const float* x     = (const float*)d_in[0];
    const int*   ei    = (const int*)d_in[1];
    const int*   batch = (const int*)d_in[2];
    const float* W1 = (const float*)d_in[3];
    const float* g1 = (const float*)d_in[5];
    const float* be1 = (const float*)d_in[6];
    const float* W2 = (const float*)d_in[7];
    const float* g2 = (const float*)d_in[9];
    const float* be2 = (const float*)d_in[10];
    const float* W3 = (const float*)d_in[11];
    const float* g3 = (const float*)d_in[13];
    const float* be3 = (const float*)d_in[14];
    const float* Wo = (const float*)d_in[15];
    const float* bo = (const float*)d_in[16];
    float* out = (float*)d_out;

    void *hp = nullptr, *aggp = nullptr, *b16p = nullptr, *whp = nullptr, *wlp = nullptr;
    cudaGetSymbolAddress(&hp, g_h);
    cudaGetSymbolAddress(&aggp, g_agg);
    cudaGetSymbolAddress(&b16p, g_b16);
    cudaGetSymbolAddress(&whp, g_wbh);
    cudaGetSymbolAddress(&wlp, g_wbl);
    float*    hbuf   = (float*)hp;
    float*    aggbuf = (float*)aggp;
    uint32_t* b16    = (uint32_t*)b16p;
    uint32_t* wh     = (uint32_t*)whp;
    uint32_t* wl     = (uint32_t*)wlp;

    // pre-conversions (independent of CSR)
    conv_x_kernel<<<(N_NODES * F_IN / 4 + 255) / 256, 256>>>(x);
    conv_wp_kernel<<<(32768 + 255) / 256, 256>>>(W1, wh + W1P_OFF, wl + W1P_OFF, F_IN, H1);
    conv_wp_kernel<<<(65536 + 255) / 256, 256>>>(W2, wh + W2P_OFF, wl + W2P_OFF, H1, H2);
    conv_wp_kernel<<<(16384 + 255) / 256, 256>>>(W3, wh + W3P_OFF, wl + W3P_OFF, H2, H3);

    // CSR build (by target) + dinv
    zero_counts_kernel<<<(N_NODES + 255) / 256, 256>>>();
    count_deg_kernel<<<(N_EDGES + 255) / 256, 256>>>(ei);
    finalize_dinv_kernel<<<(N_NODES + 255) / 256, 256>>>();
    partial_sum_kernel<<<SCAN_NB, 1024>>>();
    scan_bsum_kernel<<<1, 64>>>();
    offsets_kernel<<<SCAN_NB, 1024>>>();
    fill_csr_kernel<<<(N_EDGES + 255) / 256, 256>>>(ei);

    const int MB = (N_NODES + 127) / 128;   // 391

    // layer 1: aggX = A_hat x (bf16 msgs) ; h1 = aggX @ W1 (fp32 out, fused stats)
    gather_bf16_kernel<false><<<dim3(N_NODES / 8, 1), 256>>>(b16, aggbuf, F_IN);
    gemm_bf16_kernel<false, true, false><<<dim3(H1 / 128, MB), 256>>>(
        aggbuf, wh + W1P_OFF, wl + W1P_OFF, hbuf, nullptr, N_NODES, F_IN, H1);
    bn_finalize_kernel<<<1, H1>>>(g1, be1);

    // layer 2: h2 = relu(bn(h1)) @ W2 (bf16 out) ; agg2 = A_hat h2 (+stats)
    gemm_bf16_kernel<true, false, true><<<dim3(H2 / 128, MB), 256>>>(
        hbuf, wh + W2P_OFF, wl + W2P_OFF, nullptr, b16, N_NODES, H1, H2);
    gather_bf16_kernel<true><<<dim3(N_NODES / 8, H2 / 128), 256>>>(b16, aggbuf, H2);
    bn_finalize_kernel<<<1, H2>>>(g2, be2);

    // layer 3: h3 = relu(bn(agg2)) @ W3 (bf16 out) ; agg3 = A_hat h3 (+stats) -> g_h
    gemm_bf16_kernel<true, false, true><<<dim3(H3 / 128, MB), 256>>>(
        aggbuf, wh + W3P_OFF, wl + W3P_OFF, nullptr, b16, N_NODES, H2, H3);
    gather_bf16_kernel<true><<<dim3(N_NODES / 8, 1), 256>>>(b16, hbuf, H3);
    bn_finalize_kernel<<<1, H3>>>(g3, be3);

    // pool (BN3+ReLU fused) + output head
    zero_pool_kernel<<<(N_GRAPHS * H3 + 255) / 256, 256>>>();
    pool_kernel<<<(N_NODES + 31) / 32, 128>>>(batch);
    final_linear_kernel<<<(N_GRAPHS * N_CLS + 255) / 256, 256>>>(Wo, bo, out);
}

// round 7
// speedup vs baseline: 6.7109x; 1.0511x over previous
#include <cuda_runtime.h>
#include <cuda_bf16.h>
#include <math.h>
#include <stdint.h>

#define N_NODES 50000
#define N_EDGES 800000
#define N_GRAPHS 64
#define F_IN 128
#define H1 512
#define H2 256
#define H3 128
#define N_CLS 10
#define BN_EPS 1e-5f
#define HMAX 512
#define SCAN_NB 49   // ceil(50000/1024)

// packed-weight segment offsets ([N][K/2] uint32 layout)
#define W1P_OFF 0
#define W2P_OFF 32768          // 512*64
#define W3P_OFF 98304          // + 256*256
#define WP_TOTAL 114688        // + 128*128

// ------------------------ scratch (device globals; no allocs) ------------------------
__device__ float    g_deg[N_NODES];                    // dinv
__device__ int      g_counts[N_NODES];
__device__ int      g_cur[N_NODES];
__device__ int      g_bsum[64];
__device__ int      g_bbase[64];
__device__ int      g_offs[N_NODES + 1];
__device__ int2     g_csr[N_EDGES];                    // {src, norm bits} packed
__device__ float    g_h  [(size_t)N_NODES * HMAX];     // fp32 scratch
__device__ float    g_agg[(size_t)N_NODES * HMAX];     // fp32 scratch
__device__ uint32_t g_b16a[(size_t)N_NODES * 256];     // packed bf16x2 (F up to 512)
__device__ uint32_t g_b16b[(size_t)N_NODES * 128];     // packed bf16x2 (F up to 256)
__device__ uint32_t g_wbh[WP_TOTAL];                   // weights bf16-hi packed x2
__device__ uint32_t g_wbl[WP_TOTAL];                   // weights bf16-lo packed x2
__device__ float    g_sumf[HMAX];                      // zero-init; re-zeroed by bn_finalize
__device__ float    g_sqf [HMAX];
__device__ float    g_scale[HMAX];
__device__ float    g_shift[HMAX];
__device__ float    g_pool[N_GRAPHS * H3];
__device__ float    g_cnt [N_GRAPHS];

// ------------------------ helpers ------------------------
__device__ __forceinline__ float2 b2f(uint32_t u) {   // bf16x2 -> float2 (low = .x)
    return make_float2(__uint_as_float(u << 16), __uint_as_float(u & 0xFFFF0000u));
}

__device__ __forceinline__ uint32_t f2b2(float x, float y) {  // pack (x=low, y=high)
    __nv_bfloat162 h = __float22bfloat162_rn(make_float2(x, y));
    return *(uint32_t*)&h;
}

__device__ __forceinline__ void mma_bf16(float4& c, uint32_t a0, uint32_t a1,
                                         uint32_t a2, uint32_t a3,
                                         uint32_t b0, uint32_t b1) {
    asm volatile(
        "mma.sync.aligned.m16n8k16.row.col.f32.bf16.bf16.f32 "
        "{%0,%1,%2,%3}, {%4,%5,%6,%7}, {%8,%9}, {%0,%1,%2,%3};"
        : "+f"(c.x), "+f"(c.y), "+f"(c.z), "+f"(c.w)
        : "r"(a0), "r"(a1), "r"(a2), "r"(a3), "r"(b0), "r"(b1));
}

// ------------------------ pre-conversions ------------------------
// W [K][N] fp32 -> packed bf16 hi/lo, [N][K/2] uint32 (pair = k even/odd)
__global__ void conv_wp_kernel(const float* __restrict__ W, uint32_t* __restrict__ wh,
                               uint32_t* __restrict__ wl, int K, int N) {
    int idx = blockIdx.x * blockDim.x + threadIdx.x;
    int Kp = K >> 1;
    if (idx >= N * Kp) return;
    int n = idx / Kp, kp = idx - n * Kp;
    float w0 = W[(size_t)(2 * kp)     * N + n];
    float w1 = W[(size_t)(2 * kp + 1) * N + n];
    __nv_bfloat16 h0 = __float2bfloat16(w0);
    __nv_bfloat16 h1 = __float2bfloat16(w1);
    float l0 = w0 - __bfloat162float(h0);
    float l1 = w1 - __bfloat162float(h1);
    __nv_bfloat162 ph; ph.x = h0; ph.y = h1;
    wh[idx] = *(uint32_t*)&ph;
    wl[idx] = f2b2(l0, l1);
}

// x (50000x128 fp32) -> packed bf16x2 in g_b16b; also zero counters
__global__ void conv_x_kernel(const float* __restrict__ x) {
    int i = blockIdx.x * blockDim.x + threadIdx.x;
    if (i < N_NODES) { g_counts[i] = 0; g_cur[i] = 0; }
    if (i >= N_NODES * F_IN / 4) return;
    float4 v = *(const float4*)&x[i * 4];
    uint2 o;
    o.x = f2b2(v.x, v.y);
    o.y = f2b2(v.z, v.w);
    *(uint2*)&g_b16b[i * 2] = o;
}

// ------------------------ CSR construction ------------------------
__global__ void count_deg_kernel(const int* __restrict__ ei) {
    int e = blockIdx.x * blockDim.x + threadIdx.x;
    if (e < N_EDGES) atomicAdd(&g_counts[ei[N_EDGES + e]], 1);
}

__global__ void finalize_dinv_kernel() {
    int i = blockIdx.x * blockDim.x + threadIdx.x;
    if (i < N_NODES) g_deg[i] = rsqrtf((float)g_counts[i] + 1.0f);
}

__global__ void partial_sum_kernel() {
    __shared__ int s[1024];
    int t = threadIdx.x;
    int i = blockIdx.x * 1024 + t;
    s[t] = (i < N_NODES) ? g_counts[i] : 0;
    __syncthreads();
    for (int st = 512; st > 0; st >>= 1) {
        if (t < st) s[t] += s[t + st];
        __syncthreads();
    }
    if (t == 0) g_bsum[blockIdx.x] = s[0];
}

__global__ void scan_bsum_kernel() {
    __shared__ int s[64];
    int t = threadIdx.x;
    int v0 = (t < SCAN_NB) ? g_bsum[t] : 0;
    s[t] = v0;
    __syncthreads();
    for (int d = 1; d < 64; d <<= 1) {
        int v = (t >= d) ? s[t - d] : 0;
        __syncthreads();
        s[t] += v;
        __syncthreads();
    }
    if (t < SCAN_NB) g_bbase[t] = s[t] - v0;   // exclusive
    if (t == 0) g_offs[N_NODES] = N_EDGES;
}

__global__ void offsets_kernel() {
    __shared__ int s[1024];
    int t = threadIdx.x;
    int i = blockIdx.x * 1024 + t;
    int c = (i < N_NODES) ? g_counts[i] : 0;
    s[t] = c;
    __syncthreads();
    for (int d = 1; d < 1024; d <<= 1) {
        int v = (t >= d) ? s[t - d] : 0;
        __syncthreads();
        s[t] += v;
        __syncthreads();
    }
    if (i < N_NODES) g_offs[i] = g_bbase[blockIdx.x] + s[t] - c;
}

__global__ void fill_csr_kernel(const int* __restrict__ ei) {
    int e = blockIdx.x * blockDim.x + threadIdx.x;
    if (e >= N_EDGES) return;
    int r = ei[e];
    int c = ei[N_EDGES + e];
    int pos = g_offs[c] + atomicAdd(&g_cur[c], 1);
    g_csr[pos] = make_int2(r, __float_as_int(g_deg[r] * g_deg[c]));
}

// ------------------------ GEMM: C = f(A) @ W  (bf16 TC, W hi+lo) ------------------------
// 128x128 block, BK=16, 256 threads (8 warps: 2m x 4n, warp tile 64x32), double buffered.
#define PSTR 12

template<bool A_BF16, bool APPLY_BN, bool DO_STATS, bool OUT_BF16>
__global__ void __launch_bounds__(256, 2)
gemm_bf16_kernel(const void* __restrict__ Av,
                 const uint32_t* __restrict__ Bh, const uint32_t* __restrict__ Bl,
                 float* __restrict__ Cf, uint32_t* __restrict__ Cb,
                 int M, int K, int N) {
    __shared__ uint32_t sA [2][128 * PSTR];
    __shared__ uint32_t sBh[2][128 * PSTR];
    __shared__ uint32_t sBl[2][128 * PSTR];
    __shared__ float sSc[HMAX], sSh[HMAX];

    int t    = threadIdx.x;
    int lane = t & 31;
    int warp = t >> 5;
    int g    = lane >> 2;      // groupID
    int tig  = lane & 3;       // threadID_in_group
    int wm   = (warp & 1) * 64;
    int wn   = (warp >> 1) * 32;
    int bm   = blockIdx.y * 128;
    int bcn  = blockIdx.x * 128;
    int Kp   = K >> 1;

    if (APPLY_BN) {
        for (int i = t; i < K; i += 256) { sSc[i] = g_scale[i]; sSh[i] = g_shift[i]; }
        __syncthreads();
    }

    // loader mappings
    int am = t >> 1, ak = (t & 1) * 8;      // fp32 col base / bf16 col base
    bool arow = (bm + am) < M;
    const float*    Ap32 = (const float*)Av    + (size_t)(bm + am) * K  + ak;
    const uint32_t* Ap16 = (const uint32_t*)Av + (size_t)(bm + am) * Kp + (t & 1) * 4;
    int bnr = t >> 1, bq = (t & 1) * 4;     // k-pair base
    const uint32_t* Bhp = Bh + (size_t)(bcn + bnr) * Kp + bq;
    const uint32_t* Blp = Bl + (size_t)(bcn + bnr) * Kp + bq;

    float4 acc[4][4];
    #pragma unroll
    for (int i = 0; i < 4; i++)
        #pragma unroll
        for (int j = 0; j < 4; j++) acc[i][j] = make_float4(0.f, 0.f, 0.f, 0.f);

    uint4 ua, ubh, ubl;

    auto load_tile = [&](int k0) {
        float4 a0 = make_float4(0.f, 0.f, 0.f, 0.f);
        float4 a1 = make_float4(0.f, 0.f, 0.f, 0.f);
        if (arow) {
            if (A_BF16) {
                uint4 raw = *(const uint4*)(Ap16 + (k0 >> 1));
                float2 p0 = b2f(raw.x), p1 = b2f(raw.y);
                float2 p2 = b2f(raw.z), p3 = b2f(raw.w);
                a0 = make_float4(p0.x, p0.y, p1.x, p1.y);
                a1 = make_float4(p2.x, p2.y, p3.x, p3.y);
            } else {
                a0 = *(const float4*)(Ap32 + k0);
                a1 = *(const float4*)(Ap32 + k0 + 4);
            }
            if (APPLY_BN) {
                int kb = k0 + ak;
                a0.x = fmaxf(fmaf(a0.x, sSc[kb + 0], sSh[kb + 0]), 0.f);
                a0.y = fmaxf(fmaf(a0.y, sSc[kb + 1], sSh[kb + 1]), 0.f);
                a0.z = fmaxf(fmaf(a0.z, sSc[kb + 2], sSh[kb + 2]), 0.f);
                a0.w = fmaxf(fmaf(a0.w, sSc[kb + 3], sSh[kb + 3]), 0.f);
                a1.x = fmaxf(fmaf(a1.x, sSc[kb + 4], sSh[kb + 4]), 0.f);
                a1.y = fmaxf(fmaf(a1.y, sSc[kb + 5], sSh[kb + 5]), 0.f);
                a1.z = fmaxf(fmaf(a1.z, sSc[kb + 6], sSh[kb + 6]), 0.f);
                a1.w = fmaxf(fmaf(a1.w, sSc[kb + 7], sSh[kb + 7]), 0.f);
            }
        }
        ua.x = f2b2(a0.x, a0.y); ua.y = f2b2(a0.z, a0.w);
        ua.z = f2b2(a1.x, a1.y); ua.w = f2b2(a1.z, a1.w);
        ubh = *(const uint4*)(Bhp + (k0 >> 1));
        ubl = *(const uint4*)(Blp + (k0 >> 1));
    };

    auto store_tile = [&](int buf) {
        *(uint4*)&sA [buf][am  * PSTR + (t & 1) * 4] = ua;
        *(uint4*)&sBh[buf][bnr * PSTR + bq]          = ubh;
        *(uint4*)&sBl[buf][bnr * PSTR + bq]          = ubl;
    };

    load_tile(0);
    store_tile(0);
    __syncthreads();

    int buf = 0;
    for (int k0 = 0; k0 < K; k0 += 16) {
        bool more = (k0 + 16) < K;
        if (more) load_tile(k0 + 16);

        uint32_t af[4][4];
        #pragma unroll
        for (int i = 0; i < 4; i++) {
            int r0 = wm + 16 * i + g;
            af[i][0] = sA[buf][ r0      * PSTR + tig    ];
            af[i][1] = sA[buf][(r0 + 8) * PSTR + tig    ];
            af[i][2] = sA[buf][ r0      * PSTR + tig + 4];
            af[i][3] = sA[buf][(r0 + 8) * PSTR + tig + 4];
        }
        #pragma unroll
        for (int j = 0; j < 4; j++) {
            int nb = wn + 8 * j + g;
            uint32_t bh0 = sBh[buf][nb * PSTR + tig    ];
            uint32_t bh1 = sBh[buf][nb * PSTR + tig + 4];
            uint32_t bl0 = sBl[buf][nb * PSTR + tig    ];
            uint32_t bl1 = sBl[buf][nb * PSTR + tig + 4];
            #pragma unroll
            for (int i = 0; i < 4; i++) {
                mma_bf16(acc[i][j], af[i][0], af[i][1], af[i][2], af[i][3], bh0, bh1);
                mma_bf16(acc[i][j], af[i][0], af[i][1], af[i][2], af[i][3], bl0, bl1);
            }
        }

        if (more) store_tile(buf ^ 1);
        __syncthreads();
        buf ^= 1;
    }

    // fused BN stats: OOB rows have acc==0 so add unconditionally
    if (DO_STATS) {
        #pragma unroll
        for (int j = 0; j < 4; j++) {
            float sx = 0.f, sy = 0.f, qx = 0.f, qy = 0.f;
            #pragma unroll
            for (int i = 0; i < 4; i++) {
                sx += acc[i][j].x + acc[i][j].z;
                sy += acc[i][j].y + acc[i][j].w;
                qx += acc[i][j].x * acc[i][j].x + acc[i][j].z * acc[i][j].z;
                qy += acc[i][j].y * acc[i][j].y + acc[i][j].w * acc[i][j].w;
            }
            #pragma unroll
            for (int m = 4; m < 32; m <<= 1) {
                sx += __shfl_xor_sync(0xffffffffu, sx, m);
                sy += __shfl_xor_sync(0xffffffffu, sy, m);
                qx += __shfl_xor_sync(0xffffffffu, qx, m);
                qy += __shfl_xor_sync(0xffffffffu, qy, m);
            }
            if (lane < 4) {
                int n = bcn + wn + 8 * j + 2 * lane;
                atomicAdd(&g_sumf[n],     sx);
                atomicAdd(&g_sumf[n + 1], sy);
                atomicAdd(&g_sqf [n],     qx);
                atomicAdd(&g_sqf [n + 1], qy);
            }
        }
    }

    // epilogue
    #pragma unroll
    for (int i = 0; i < 4; i++) {
        int m0 = bm + wm + 16 * i + g;
        int m1 = m0 + 8;
        #pragma unroll
        for (int j = 0; j < 4; j++) {
            int n = bcn + wn + 8 * j + 2 * tig;
            if (OUT_BF16) {
                if (m0 < M) Cb[((size_t)m0 * N + n) >> 1] = f2b2(acc[i][j].x, acc[i][j].y);
                if (m1 < M) Cb[((size_t)m1 * N + n) >> 1] = f2b2(acc[i][j].z, acc[i][j].w);
            } else {
                if (m0 < M) *(float2*)&Cf[(size_t)m0 * N + n] = make_float2(acc[i][j].x, acc[i][j].y);
                if (m1 < M) *(float2*)&Cf[(size_t)m1 * N + n] = make_float2(acc[i][j].z, acc[i][j].w);
            }
        }
    }
}

// ------------------------ CSR gather over bf16 rows (+ optional fused BN stats) ------------------------
// one warp per (node, 128-feature chunk); grid=(6250, F/128), block=256 (8 nodes)
template<bool DO_STATS>
__global__ void gather_bf16_kernel(const uint32_t* __restrict__ src,
                                   float* __restrict__ dst, int F) {
    __shared__ float s_ps[8][128];
    __shared__ float s_pq[8][128];

    int t    = threadIdx.x;
    int lane = t & 31;
    int w    = t >> 5;
    int node = blockIdx.x * 8 + w;          // 50000 = 6250*8
    int fb   = blockIdx.y << 7;
    int f0   = fb + lane * 4;
    int Fu   = F >> 1;                       // row pitch in uint32
    int f0u  = (f0 >> 1);

    float di = g_deg[node];
    float sl = di * di;
    uint2 sv = *(const uint2*)&src[(size_t)node * Fu + f0u];
    float2 sa = b2f(sv.x), sb = b2f(sv.y);
    float4 acc = make_float4(sa.x * sl, sa.y * sl, sb.x * sl, sb.y * sl);

    int j   = g_offs[node];
    int end = g_offs[node + 1];
    for (; j + 4 <= end; j += 4) {
        int2 e0 = g_csr[j],     e1 = g_csr[j + 1];
        int2 e2 = g_csr[j + 2], e3 = g_csr[j + 3];
        float n0 = __int_as_float(e0.y), n1 = __int_as_float(e1.y);
        float n2 = __int_as_float(e2.y), n3 = __int_as_float(e3.y);
        uint2 u0 = *(const uint2*)&src[(size_t)e0.x * Fu + f0u];
        uint2 u1 = *(const uint2*)&src[(size_t)e1.x * Fu + f0u];
        uint2 u2 = *(const uint2*)&src[(size_t)e2.x * Fu + f0u];
        uint2 u3 = *(const uint2*)&src[(size_t)e3.x * Fu + f0u];
        float2 a0 = b2f(u0.x), b0 = b2f(u0.y);
        float2 a1 = b2f(u1.x), b1 = b2f(u1.y);
        float2 a2 = b2f(u2.x), b2 = b2f(u2.y);
        float2 a3 = b2f(u3.x), b3 = b2f(u3.y);
        acc.x = fmaf(a0.x, n0, acc.x); acc.y = fmaf(a0.y, n0, acc.y);
        acc.z = fmaf(b0.x, n0, acc.z); acc.w = fmaf(b0.y, n0, acc.w);
        acc.x = fmaf(a1.x, n1, acc.x); acc.y = fmaf(a1.y, n1, acc.y);
        acc.z = fmaf(b1.x, n1, acc.z); acc.w = fmaf(b1.y, n1, acc.w);
        acc.x = fmaf(a2.x, n2, acc.x); acc.y = fmaf(a2.y, n2, acc.y);
        acc.z = fmaf(b2.x, n2, acc.z); acc.w = fmaf(b2.y, n2, acc.w);
        acc.x = fmaf(a3.x, n3, acc.x); acc.y = fmaf(a3.y, n3, acc.y);
        acc.z = fmaf(b3.x, n3, acc.z); acc.w = fmaf(b3.y, n3, acc.w);
    }
    for (; j < end; j++) {
        int2 e0 = g_csr[j];
        float n0 = __int_as_float(e0.y);
        uint2 u0 = *(const uint2*)&src[(size_t)e0.x * Fu + f0u];
        float2 a0 = b2f(u0.x), b0 = b2f(u0.y);
        acc.x = fmaf(a0.x, n0, acc.x); acc.y = fmaf(a0.y, n0, acc.y);
        acc.z = fmaf(b0.x, n0, acc.z); acc.w = fmaf(b0.y, n0, acc.w);
    }
    *(float4*)&dst[(size_t)node * F + f0] = acc;

    if (DO_STATS) {
        *(float4*)&s_ps[w][lane * 4] = acc;
        *(float4*)&s_pq[w][lane * 4] = make_float4(acc.x * acc.x, acc.y * acc.y,
                                                   acc.z * acc.z, acc.w * acc.w);
        __syncthreads();
        if (t < 128) {
            float s = 0.f;
            #pragma unroll
            for (int ww = 0; ww < 8; ww++) s += s_ps[ww][t];
            atomicAdd(&g_sumf[fb + t], s);
        } else {
            int t2 = t - 128;
            float s = 0.f;
            #pragma unroll
            for (int ww = 0; ww < 8; ww++) s += s_pq[ww][t2];
            atomicAdd(&g_sqf[fb + t2], s);
        }
    }
}

// compute scale/shift, then re-zero the accumulators for the next use/replay
template<bool ZERO_POOL>
__global__ void bn_finalize_kernel(const float* __restrict__ gamma,
                                   const float* __restrict__ beta) {
    int f = threadIdx.x;
    double mean = (double)g_sumf[f] * (1.0 / N_NODES);
    double var  = (double)g_sqf[f] * (1.0 / N_NODES) - mean * mean;
    float scale = gamma[f] * rsqrtf((float)var + BN_EPS);
    g_scale[f] = scale;
    g_shift[f] = beta[f] - (float)mean * scale;
    g_sumf[f] = 0.f;
    g_sqf[f]  = 0.f;
    if (ZERO_POOL) {
        for (int i = f; i < N_GRAPHS * H3; i += H3) g_pool[i] = 0.f;
        if (f < N_GRAPHS) g_cnt[f] = 0.f;
    }
}

// ------------------------ pool (fused BN3+ReLU, run-length atomics) ------------------------
// 128 threads/block, 32 nodes/block; batch is sorted -> few graph transitions
__global__ void pool_kernel(const int* __restrict__ batch) {
    int f  = threadIdx.x;
    int n0 = blockIdx.x * 32;
    int ne = min(n0 + 32, N_NODES);
    float sc = g_scale[f], sh = g_shift[f];
    int curg = batch[n0];
    float run = 0.f, cnt = 0.f;
    for (int n = n0; n < ne; n++) {
        int g = batch[n];
        if (g != curg) {
            atomicAdd(&g_pool[curg * H3 + f], run);
            if (f == 0) atomicAdd(&g_cnt[curg], cnt);
            run = 0.f; cnt = 0.f; curg = g;
        }
        float v = g_h[(size_t)n * H3 + f];
        run += fmaxf(fmaf(v, sc, sh), 0.f);
        cnt += 1.f;
    }
    atomicAdd(&g_pool[curg * H3 + f], run);
    if (f == 0) atomicAdd(&g_cnt[curg], cnt);
}

__global__ void final_linear_kernel(const float* __restrict__ Wo,
                                    const float* __restrict__ bo,
                                    float* __restrict__ out) {
    int t = blockIdx.x * blockDim.x + threadIdx.x;
    if (t >= N_GRAPHS * N_CLS) return;
    int g = t / N_CLS;
    int c = t % N_CLS;
    float inv_cnt = 1.0f / fmaxf(g_cnt[g], 1.0f);
    float s = 0.0f;
    #pragma unroll 8
    for (int f = 0; f < H3; f++)
        s += g_pool[g * H3 + f] * Wo[f * N_CLS + c];
    out[t] = s * inv_cnt + bo[c];
}

// ------------------------ host orchestration ------------------------
extern "C" void kernel_launch(void* const* d_in, const int* in_sizes, int n_in,
                              void* d_out, int out_size) {
    const float* x     = (const float*)d_in[0];
    const int*   ei    = (const int*)d_in[1];
    const int*   batch = (const int*)d_in[2];
    const float* W1 = (const float*)d_in[3];
    const float* g1 = (const float*)d_in[5];
    const float* be1 = (const float*)d_in[6];
    const float* W2 = (const float*)d_in[7];
    const float* g2 = (const float*)d_in[9];
    const float* be2 = (const float*)d_in[10];
    const float* W3 = (const float*)d_in[11];
    const float* g3 = (const float*)d_in[13];
    const float* be3 = (const float*)d_in[14];
    const float* Wo = (const float*)d_in[15];
    const float* bo = (const float*)d_in[16];
    float* out = (float*)d_out;

    void *hp = nullptr, *aggp = nullptr, *ap = nullptr, *bp = nullptr, *whp = nullptr, *wlp = nullptr;
    cudaGetSymbolAddress(&hp, g_h);
    cudaGetSymbolAddress(&aggp, g_agg);
    cudaGetSymbolAddress(&ap, g_b16a);
    cudaGetSymbolAddress(&bp, g_b16b);
    cudaGetSymbolAddress(&whp, g_wbh);
    cudaGetSymbolAddress(&wlp, g_wbl);
    float*    hbuf   = (float*)hp;
    float*    aggbuf = (float*)aggp;
    uint32_t* b16a   = (uint32_t*)ap;
    uint32_t* b16b   = (uint32_t*)bp;
    uint32_t* wh     = (uint32_t*)whp;
    uint32_t* wl     = (uint32_t*)wlp;

    // pre-conversions (independent of CSR); conv_x also zeros counters
    conv_x_kernel<<<(N_NODES * F_IN / 4 + 255) / 256, 256>>>(x);
    conv_wp_kernel<<<(32768 + 255) / 256, 256>>>(W1, wh + W1P_OFF, wl + W1P_OFF, F_IN, H1);
    conv_wp_kernel<<<(65536 + 255) / 256, 256>>>(W2, wh + W2P_OFF, wl + W2P_OFF, H1, H2);
    conv_wp_kernel<<<(16384 + 255) / 256, 256>>>(W3, wh + W3P_OFF, wl + W3P_OFF, H2, H3);

    // CSR build (by target) + dinv
    count_deg_kernel<<<(N_EDGES + 255) / 256, 256>>>(ei);
    finalize_dinv_kernel<<<(N_NODES + 255) / 256, 256>>>();
    partial_sum_kernel<<<SCAN_NB, 1024>>>();
    scan_bsum_kernel<<<1, 64>>>();
    offsets_kernel<<<SCAN_NB, 1024>>>();
    fill_csr_kernel<<<(N_EDGES + 255) / 256, 256>>>(ei);

    const int MB = (N_NODES + 127) / 128;   // 391

    // layer 1: aggX = A_hat x (bf16 msgs) ; h1 = aggX @ W1 (bf16 out, fused exact stats)
    gather_bf16_kernel<false><<<dim3(N_NODES / 8, 1), 256>>>(b16b, aggbuf, F_IN);
    gemm_bf16_kernel<false, false, true, true><<<dim3(H1 / 128, MB), 256>>>(
        aggbuf, wh + W1P_OFF, wl + W1P_OFF, nullptr, b16a, N_NODES, F_IN, H1);
    bn_finalize_kernel<false><<<1, H1>>>(g1, be1);

    // layer 2: h2 = relu(bn(h1_bf16)) @ W2 (bf16 out) ; agg2 = A_hat h2 (+stats)
    gemm_bf16_kernel<true, true, false, true><<<dim3(H2 / 128, MB), 256>>>(
        b16a, wh + W2P_OFF, wl + W2P_OFF, nullptr, b16b, N_NODES, H1, H2);
    gather_bf16_kernel<true><<<dim3(N_NODES / 8, H2 / 128), 256>>>(b16b, aggbuf, H2);
    bn_finalize_kernel<false><<<1, H2>>>(g2, be2);

    // layer 3: h3 = relu(bn(agg2)) @ W3 (bf16 out) ; agg3 = A_hat h3 (+stats) -> g_h
    gemm_bf16_kernel<false, true, false, true><<<dim3(H3 / 128, MB), 256>>>(
        aggbuf, wh + W3P_OFF, wl + W3P_OFF, nullptr, b16b, N_NODES, H2, H3);
    gather_bf16_kernel<true><<<dim3(N_NODES / 8, 1), 256>>>(b16b, hbuf, H3);
    bn_finalize_kernel<true><<<1, H3>>>(g3, be3);   // also zeros pool

    // pool (BN3+ReLU fused) + output head
    pool_kernel<<<(N_NODES + 31) / 32, 128>>>(batch);
    final_linear_kernel<<<(N_GRAPHS * N_CLS + 255) / 256, 256>>>(Wo, bo, out);
}

// round 8
// speedup vs baseline: 7.0135x; 1.0451x over previous
#include <cuda_runtime.h>
#include <cuda_bf16.h>
#include <math.h>
#include <stdint.h>

#define N_NODES 50000
#define N_EDGES 800000
#define N_GRAPHS 64
#define F_IN 128
#define H1 512
#define H2 256
#define H3 128
#define N_CLS 10
#define BN_EPS 1e-5f
#define HMAX 512
#define SCAN_NB 49   // ceil(50000/1024)

// packed-weight segment offsets ([N][K/2] uint32 layout)
#define W1P_OFF 0
#define W2P_OFF 32768          // 512*64
#define W3P_OFF 98304          // + 256*256
#define WP_TOTAL 114688        // + 128*128

// ------------------------ scratch (device globals; no allocs) ------------------------
__device__ float    g_deg[N_NODES];                    // dinv
__device__ int      g_counts[N_NODES];
__device__ int      g_cur[N_NODES];
__device__ int      g_bsum[64];
__device__ int      g_bbase[64];
__device__ int      g_offs[N_NODES + 1];
__device__ int2     g_csr[N_EDGES];                    // {src, norm bits} packed
__device__ uint32_t g_scr[(size_t)N_NODES * 128];      // bf16x2 scratch (aggX/agg2)
__device__ uint32_t g_h3 [(size_t)N_NODES * 64];       // bf16x2 agg3 (pool input)
__device__ uint32_t g_b16a[(size_t)N_NODES * 256];     // bf16x2 (h1, up to F=512)
__device__ uint32_t g_b16b[(size_t)N_NODES * 128];     // bf16x2 (x / h2, up to F=256)
__device__ uint32_t g_wbh[WP_TOTAL];                   // weights bf16-hi packed x2
__device__ uint32_t g_wbl[WP_TOTAL];                   // weights bf16-lo packed x2
__device__ float    g_sumf[HMAX];                      // zero-init; re-zeroed by bn_finalize
__device__ float    g_sqf [HMAX];
__device__ float    g_scale[HMAX];
__device__ float    g_shift[HMAX];
__device__ float    g_pool[N_GRAPHS * H3];
__device__ float    g_cnt [N_GRAPHS];

// ------------------------ helpers ------------------------
__device__ __forceinline__ float2 b2f(uint32_t u) {   // bf16x2 -> float2 (low = .x)
    return make_float2(__uint_as_float(u << 16), __uint_as_float(u & 0xFFFF0000u));
}

__device__ __forceinline__ uint32_t f2b2(float x, float y) {  // pack (x=low, y=high)
    __nv_bfloat162 h = __float22bfloat162_rn(make_float2(x, y));
    return *(uint32_t*)&h;
}

__device__ __forceinline__ void mma_bf16(float4& c, uint32_t a0, uint32_t a1,
                                         uint32_t a2, uint32_t a3,
                                         uint32_t b0, uint32_t b1) {
    asm volatile(
        "mma.sync.aligned.m16n8k16.row.col.f32.bf16.bf16.f32 "
        "{%0,%1,%2,%3}, {%4,%5,%6,%7}, {%8,%9}, {%0,%1,%2,%3};"
        : "+f"(c.x), "+f"(c.y), "+f"(c.z), "+f"(c.w)
        : "r"(a0), "r"(a1), "r"(a2), "r"(a3), "r"(b0), "r"(b1));
}

// ------------------------ pre-conversions ------------------------
// W [K][N] fp32 -> packed bf16 hi/lo, [N][K/2] uint32 (pair = k even/odd)
__global__ void conv_wp_kernel(const float* __restrict__ W, uint32_t* __restrict__ wh,
                               uint32_t* __restrict__ wl, int K, int N) {
    int idx = blockIdx.x * blockDim.x + threadIdx.x;
    int Kp = K >> 1;
    if (idx >= N * Kp) return;
    int n = idx / Kp, kp = idx - n * Kp;
    float w0 = W[(size_t)(2 * kp)     * N + n];
    float w1 = W[(size_t)(2 * kp + 1) * N + n];
    __nv_bfloat16 h0 = __float2bfloat16(w0);
    __nv_bfloat16 h1 = __float2bfloat16(w1);
    float l0 = w0 - __bfloat162float(h0);
    float l1 = w1 - __bfloat162float(h1);
    __nv_bfloat162 ph; ph.x = h0; ph.y = h1;
    wh[idx] = *(uint32_t*)&ph;
    wl[idx] = f2b2(l0, l1);
}

// x (50000x128 fp32) -> packed bf16x2 in g_b16b; also zero counters
__global__ void conv_x_kernel(const float* __restrict__ x) {
    int i = blockIdx.x * blockDim.x + threadIdx.x;
    if (i < N_NODES) { g_counts[i] = 0; g_cur[i] = 0; }
    if (i >= N_NODES * F_IN / 4) return;
    float4 v = *(const float4*)&x[i * 4];
    uint2 o;
    o.x = f2b2(v.x, v.y);
    o.y = f2b2(v.z, v.w);
    *(uint2*)&g_b16b[i * 2] = o;
}

// ------------------------ CSR construction ------------------------
__global__ void count_deg_kernel(const int* __restrict__ ei) {
    int e = blockIdx.x * blockDim.x + threadIdx.x;
    if (e < N_EDGES) atomicAdd(&g_counts[ei[N_EDGES + e]], 1);
}

// fused: dinv + per-block partial sums of counts
__global__ void partial_sum_kernel() {
    __shared__ int s[1024];
    int t = threadIdx.x;
    int i = blockIdx.x * 1024 + t;
    int c = (i < N_NODES) ? g_counts[i] : 0;
    if (i < N_NODES) g_deg[i] = rsqrtf((float)c + 1.0f);
    s[t] = c;
    __syncthreads();
    for (int st = 512; st > 0; st >>= 1) {
        if (t < st) s[t] += s[t + st];
        __syncthreads();
    }
    if (t == 0) g_bsum[blockIdx.x] = s[0];
}

__global__ void scan_bsum_kernel() {
    __shared__ int s[64];
    int t = threadIdx.x;
    int v0 = (t < SCAN_NB) ? g_bsum[t] : 0;
    s[t] = v0;
    __syncthreads();
    for (int d = 1; d < 64; d <<= 1) {
        int v = (t >= d) ? s[t - d] : 0;
        __syncthreads();
        s[t] += v;
        __syncthreads();
    }
    if (t < SCAN_NB) g_bbase[t] = s[t] - v0;   // exclusive
    if (t == 0) g_offs[N_NODES] = N_EDGES;
}

__global__ void offsets_kernel() {
    __shared__ int s[1024];
    int t = threadIdx.x;
    int i = blockIdx.x * 1024 + t;
    int c = (i < N_NODES) ? g_counts[i] : 0;
    s[t] = c;
    __syncthreads();
    for (int d = 1; d < 1024; d <<= 1) {
        int v = (t >= d) ? s[t - d] : 0;
        __syncthreads();
        s[t] += v;
        __syncthreads();
    }
    if (i < N_NODES) g_offs[i] = g_bbase[blockIdx.x] + s[t] - c;
}

__global__ void fill_csr_kernel(const int* __restrict__ ei) {
    int e = blockIdx.x * blockDim.x + threadIdx.x;
    if (e >= N_EDGES) return;
    int r = ei[e];
    int c = ei[N_EDGES + e];
    int pos = g_offs[c] + atomicAdd(&g_cur[c], 1);
    g_csr[pos] = make_int2(r, __float_as_int(g_deg[r] * g_deg[c]));
}

// ------------------------ GEMM: C = f(A) @ W  (bf16 TC, W hi+lo, A bf16) ------------------------
// 128x128 block, BK=16, 256 threads (8 warps: 2m x 4n, warp tile 64x32), double buffered.
#define PSTR 12

template<bool APPLY_BN, bool DO_STATS>
__global__ void __launch_bounds__(256, 2)
gemm_bf16_kernel(const uint32_t* __restrict__ Ab,
                 const uint32_t* __restrict__ Bh, const uint32_t* __restrict__ Bl,
                 uint32_t* __restrict__ Cb,
                 int M, int K, int N) {
    __shared__ uint32_t sA [2][128 * PSTR];
    __shared__ uint32_t sBh[2][128 * PSTR];
    __shared__ uint32_t sBl[2][128 * PSTR];
    __shared__ float sSc[HMAX], sSh[HMAX];

    int t    = threadIdx.x;
    int lane = t & 31;
    int warp = t >> 5;
    int g    = lane >> 2;      // groupID
    int tig  = lane & 3;       // threadID_in_group
    int wm   = (warp & 1) * 64;
    int wn   = (warp >> 1) * 32;
    int bm   = blockIdx.y * 128;
    int bcn  = blockIdx.x * 128;
    int Kp   = K >> 1;

    if (APPLY_BN) {
        for (int i = t; i < K; i += 256) { sSc[i] = g_scale[i]; sSh[i] = g_shift[i]; }
        __syncthreads();
    }

    // loader mappings
    int am = t >> 1, ak = (t & 1) * 8;
    bool arow = (bm + am) < M;
    const uint32_t* Ap = Ab + (size_t)(bm + am) * Kp + (t & 1) * 4;
    int bnr = t >> 1, bq = (t & 1) * 4;
    const uint32_t* Bhp = Bh + (size_t)(bcn + bnr) * Kp + bq;
    const uint32_t* Blp = Bl + (size_t)(bcn + bnr) * Kp + bq;

    float4 acc[4][4];
    #pragma unroll
    for (int i = 0; i < 4; i++)
        #pragma unroll
        for (int j = 0; j < 4; j++) acc[i][j] = make_float4(0.f, 0.f, 0.f, 0.f);

    uint4 ua, ubh, ubl;

    auto load_tile = [&](int k0) {
        if (arow) {
            uint4 raw = *(const uint4*)(Ap + (k0 >> 1));
            if (APPLY_BN) {
                int kb = k0 + ak;
                float2 p0 = b2f(raw.x), p1 = b2f(raw.y);
                float2 p2 = b2f(raw.z), p3 = b2f(raw.w);
                p0.x = fmaxf(fmaf(p0.x, sSc[kb + 0], sSh[kb + 0]), 0.f);
                p0.y = fmaxf(fmaf(p0.y, sSc[kb + 1], sSh[kb + 1]), 0.f);
                p1.x = fmaxf(fmaf(p1.x, sSc[kb + 2], sSh[kb + 2]), 0.f);
                p1.y = fmaxf(fmaf(p1.y, sSc[kb + 3], sSh[kb + 3]), 0.f);
                p2.x = fmaxf(fmaf(p2.x, sSc[kb + 4], sSh[kb + 4]), 0.f);
                p2.y = fmaxf(fmaf(p2.y, sSc[kb + 5], sSh[kb + 5]), 0.f);
                p3.x = fmaxf(fmaf(p3.x, sSc[kb + 6], sSh[kb + 6]), 0.f);
                p3.y = fmaxf(fmaf(p3.y, sSc[kb + 7], sSh[kb + 7]), 0.f);
                ua.x = f2b2(p0.x, p0.y); ua.y = f2b2(p1.x, p1.y);
                ua.z = f2b2(p2.x, p2.y); ua.w = f2b2(p3.x, p3.y);
            } else {
                ua = raw;
            }
        } else {
            ua = make_uint4(0u, 0u, 0u, 0u);
        }
        ubh = *(const uint4*)(Bhp + (k0 >> 1));
        ubl = *(const uint4*)(Blp + (k0 >> 1));
    };

    auto store_tile = [&](int buf) {
        *(uint4*)&sA [buf][am  * PSTR + (t & 1) * 4] = ua;
        *(uint4*)&sBh[buf][bnr * PSTR + bq]          = ubh;
        *(uint4*)&sBl[buf][bnr * PSTR + bq]          = ubl;
    };

    load_tile(0);
    store_tile(0);
    __syncthreads();

    int buf = 0;
    for (int k0 = 0; k0 < K; k0 += 16) {
        bool more = (k0 + 16) < K;
        if (more) load_tile(k0 + 16);

        uint32_t af[4][4];
        #pragma unroll
        for (int i = 0; i < 4; i++) {
            int r0 = wm + 16 * i + g;
            af[i][0] = sA[buf][ r0      * PSTR + tig    ];
            af[i][1] = sA[buf][(r0 + 8) * PSTR + tig    ];
            af[i][2] = sA[buf][ r0      * PSTR + tig + 4];
            af[i][3] = sA[buf][(r0 + 8) * PSTR + tig + 4];
        }
        #pragma unroll
        for (int j = 0; j < 4; j++) {
            int nb = wn + 8 * j + g;
            uint32_t bh0 = sBh[buf][nb * PSTR + tig    ];
            uint32_t bh1 = sBh[buf][nb * PSTR + tig + 4];
            uint32_t bl0 = sBl[buf][nb * PSTR + tig    ];
            uint32_t bl1 = sBl[buf][nb * PSTR + tig + 4];
            #pragma unroll
            for (int i = 0; i < 4; i++) {
                mma_bf16(acc[i][j], af[i][0], af[i][1], af[i][2], af[i][3], bh0, bh1);
                mma_bf16(acc[i][j], af[i][0], af[i][1], af[i][2], af[i][3], bl0, bl1);
            }
        }

        if (more) store_tile(buf ^ 1);
        __syncthreads();
        buf ^= 1;
    }

    // fused BN stats (exact fp32 accumulators): OOB rows contribute 0
    if (DO_STATS) {
        #pragma unroll
        for (int j = 0; j < 4; j++) {
            float sx = 0.f, sy = 0.f, qx = 0.f, qy = 0.f;
            #pragma unroll
            for (int i = 0; i < 4; i++) {
                sx += acc[i][j].x + acc[i][j].z;
                sy += acc[i][j].y + acc[i][j].w;
                qx += acc[i][j].x * acc[i][j].x + acc[i][j].z * acc[i][j].z;
                qy += acc[i][j].y * acc[i][j].y + acc[i][j].w * acc[i][j].w;
            }
            #pragma unroll
            for (int m = 4; m < 32; m <<= 1) {
                sx += __shfl_xor_sync(0xffffffffu, sx, m);
                sy += __shfl_xor_sync(0xffffffffu, sy, m);
                qx += __shfl_xor_sync(0xffffffffu, qx, m);
                qy += __shfl_xor_sync(0xffffffffu, qy, m);
            }
            if (lane < 4) {
                int n = bcn + wn + 8 * j + 2 * lane;
                atomicAdd(&g_sumf[n],     sx);
                atomicAdd(&g_sumf[n + 1], sy);
                atomicAdd(&g_sqf [n],     qx);
                atomicAdd(&g_sqf [n + 1], qy);
            }
        }
    }

    // epilogue: bf16 packed store
    #pragma unroll
    for (int i = 0; i < 4; i++) {
        int m0 = bm + wm + 16 * i + g;
        int m1 = m0 + 8;
        #pragma unroll
        for (int j = 0; j < 4; j++) {
            int n = bcn + wn + 8 * j + 2 * tig;
            if (m0 < M) Cb[((size_t)m0 * N + n) >> 1] = f2b2(acc[i][j].x, acc[i][j].y);
            if (m1 < M) Cb[((size_t)m1 * N + n) >> 1] = f2b2(acc[i][j].z, acc[i][j].w);
        }
    }
}

// ------------------------ CSR gather over bf16 rows -> bf16 out (+ optional stats) ------------------------
// one warp per (node, 128-feature chunk); grid=(6250, F/128), block=256 (8 nodes)
template<bool DO_STATS>
__global__ void gather_bf16_kernel(const uint32_t* __restrict__ src,
                                   uint32_t* __restrict__ dst, int F) {
    __shared__ float s_ps[8][128];
    __shared__ float s_pq[8][128];

    int t    = threadIdx.x;
    int lane = t & 31;
    int w    = t >> 5;
    int node = blockIdx.x * 8 + w;          // 50000 = 6250*8
    int fb   = blockIdx.y << 7;
    int f0   = fb + lane * 4;
    int Fu   = F >> 1;                       // row pitch in uint32
    int f0u  = (f0 >> 1);

    float di = g_deg[node];
    float sl = di * di;
    uint2 sv = *(const uint2*)&src[(size_t)node * Fu + f0u];
    float2 sa = b2f(sv.x), sb = b2f(sv.y);
    float4 acc = make_float4(sa.x * sl, sa.y * sl, sb.x * sl, sb.y * sl);

    int j   = g_offs[node];
    int end = g_offs[node + 1];
    for (; j + 4 <= end; j += 4) {
        int2 e0 = g_csr[j],     e1 = g_csr[j + 1];
        int2 e2 = g_csr[j + 2], e3 = g_csr[j + 3];
        float n0 = __int_as_float(e0.y), n1 = __int_as_float(e1.y);
        float n2 = __int_as_float(e2.y), n3 = __int_as_float(e3.y);
        uint2 u0 = *(const uint2*)&src[(size_t)e0.x * Fu + f0u];
        uint2 u1 = *(const uint2*)&src[(size_t)e1.x * Fu + f0u];
        uint2 u2 = *(const uint2*)&src[(size_t)e2.x * Fu + f0u];
        uint2 u3 = *(const uint2*)&src[(size_t)e3.x * Fu + f0u];
        float2 a0 = b2f(u0.x), b0 = b2f(u0.y);
        float2 a1 = b2f(u1.x), b1 = b2f(u1.y);
        float2 a2 = b2f(u2.x), b2 = b2f(u2.y);
        float2 a3 = b2f(u3.x), b3 = b2f(u3.y);
        acc.x = fmaf(a0.x, n0, acc.x); acc.y = fmaf(a0.y, n0, acc.y);
        acc.z = fmaf(b0.x, n0, acc.z); acc.w = fmaf(b0.y, n0, acc.w);
        acc.x = fmaf(a1.x, n1, acc.x); acc.y = fmaf(a1.y, n1, acc.y);
        acc.z = fmaf(b1.x, n1, acc.z); acc.w = fmaf(b1.y, n1, acc.w);
        acc.x = fmaf(a2.x, n2, acc.x); acc.y = fmaf(a2.y, n2, acc.y);
        acc.z = fmaf(b2.x, n2, acc.z); acc.w = fmaf(b2.y, n2, acc.w);
        acc.x = fmaf(a3.x, n3, acc.x); acc.y = fmaf(a3.y, n3, acc.y);
        acc.z = fmaf(b3.x, n3, acc.z); acc.w = fmaf(b3.y, n3, acc.w);
    }
    for (; j < end; j++) {
        int2 e0 = g_csr[j];
        float n0 = __int_as_float(e0.y);
        uint2 u0 = *(const uint2*)&src[(size_t)e0.x * Fu + f0u];
        float2 a0 = b2f(u0.x), b0 = b2f(u0.y);
        acc.x = fmaf(a0.x, n0, acc.x); acc.y = fmaf(a0.y, n0, acc.y);
        acc.z = fmaf(b0.x, n0, acc.z); acc.w = fmaf(b0.y, n0, acc.w);
    }
    // bf16 packed store (stats below use the exact fp32 acc)
    uint2 outv;
    outv.x = f2b2(acc.x, acc.y);
    outv.y = f2b2(acc.z, acc.w);
    *(uint2*)&dst[(size_t)node * Fu + f0u] = outv;

    if (DO_STATS) {
        *(float4*)&s_ps[w][lane * 4] = acc;
        *(float4*)&s_pq[w][lane * 4] = make_float4(acc.x * acc.x, acc.y * acc.y,
                                                   acc.z * acc.z, acc.w * acc.w);
        __syncthreads();
        if (t < 128) {
            float s = 0.f;
            #pragma unroll
            for (int ww = 0; ww < 8; ww++) s += s_ps[ww][t];
            atomicAdd(&g_sumf[fb + t], s);
        } else {
            int t2 = t - 128;
            float s = 0.f;
            #pragma unroll
            for (int ww = 0; ww < 8; ww++) s += s_pq[ww][t2];
            atomicAdd(&g_sqf[fb + t2], s);
        }
    }
}

// compute scale/shift, then re-zero the accumulators for the next use/replay
template<bool ZERO_POOL>
__global__ void bn_finalize_kernel(const float* __restrict__ gamma,
                                   const float* __restrict__ beta) {
    int f = threadIdx.x;
    double mean = (double)g_sumf[f] * (1.0 / N_NODES);
    double var  = (double)g_sqf[f] * (1.0 / N_NODES) - mean * mean;
    float scale = gamma[f] * rsqrtf((float)var + BN_EPS);
    g_scale[f] = scale;
    g_shift[f] = beta[f] - (float)mean * scale;
    g_sumf[f] = 0.f;
    g_sqf[f]  = 0.f;
    if (ZERO_POOL) {
        for (int i = f; i < N_GRAPHS * H3; i += H3) g_pool[i] = 0.f;
        if (f < N_GRAPHS) g_cnt[f] = 0.f;
    }
}

// ------------------------ pool (fused BN3+ReLU, run-length atomics; bf16 input) ------------------------
// 128 threads/block, 32 nodes/block; batch is sorted -> few graph transitions
__global__ void pool_kernel(const int* __restrict__ batch) {
    int f  = threadIdx.x;
    int n0 = blockIdx.x * 32;
    int ne = min(n0 + 32, N_NODES);
    float sc = g_scale[f], sh = g_shift[f];
    const __nv_bfloat16* h3 = (const __nv_bfloat16*)g_h3;
    int curg = batch[n0];
    float run = 0.f, cnt = 0.f;
    for (int n = n0; n < ne; n++) {
        int g = batch[n];
        if (g != curg) {
            atomicAdd(&g_pool[curg * H3 + f], run);
            if (f == 0) atomicAdd(&g_cnt[curg], cnt);
            run = 0.f; cnt = 0.f; curg = g;
        }
        float v = __bfloat162float(h3[(size_t)n * H3 + f]);
        run += fmaxf(fmaf(v, sc, sh), 0.f);
        cnt += 1.f;
    }
    atomicAdd(&g_pool[curg * H3 + f], run);
    if (f == 0) atomicAdd(&g_cnt[curg], cnt);
}

__global__ void final_linear_kernel(const float* __restrict__ Wo,
                                    const float* __restrict__ bo,
                                    float* __restrict__ out) {
    int t = blockIdx.x * blockDim.x + threadIdx.x;
    if (t >= N_GRAPHS * N_CLS) return;
    int g = t / N_CLS;
    int c = t % N_CLS;
    float inv_cnt = 1.0f / fmaxf(g_cnt[g], 1.0f);
    float s = 0.0f;
    #pragma unroll 8
    for (int f = 0; f < H3; f++)
        s += g_pool[g * H3 + f] * Wo[f * N_CLS + c];
    out[t] = s * inv_cnt + bo[c];
}

// ------------------------ host orchestration ------------------------
extern "C" void kernel_launch(void* const* d_in, const int* in_sizes, int n_in,
                              void* d_out, int out_size) {
    const float* x     = (const float*)d_in[0];
    const int*   ei    = (const int*)d_in[1];
    const int*   batch = (const int*)d_in[2];
    const float* W1 = (const float*)d_in[3];
    const float* g1 = (const float*)d_in[5];
    const float* be1 = (const float*)d_in[6];
    const float* W2 = (const float*)d_in[7];
    const float* g2 = (const float*)d_in[9];
    const float* be2 = (const float*)d_in[10];
    const float* W3 = (const float*)d_in[11];
    const float* g3 = (const float*)d_in[13];
    const float* be3 = (const float*)d_in[14];
    const float* Wo = (const float*)d_in[15];
    const float* bo = (const float*)d_in[16];
    float* out = (float*)d_out;

    void *scrp = nullptr, *h3p = nullptr, *ap = nullptr, *bp = nullptr, *whp = nullptr, *wlp = nullptr;
    cudaGetSymbolAddress(&scrp, g_scr);
    cudaGetSymbolAddress(&h3p, g_h3);
    cudaGetSymbolAddress(&ap, g_b16a);
    cudaGetSymbolAddress(&bp, g_b16b);
    cudaGetSymbolAddress(&whp, g_wbh);
    cudaGetSymbolAddress(&wlp, g_wbl);
    uint32_t* scr  = (uint32_t*)scrp;   // aggX (F=128) then agg2 (F=256)
    uint32_t* h3b  = (uint32_t*)h3p;    // agg3 (F=128)
    uint32_t* b16a = (uint32_t*)ap;     // h1 (F=512), then h3 (F=128)
    uint32_t* b16b = (uint32_t*)bp;     // x (F=128), then h2 (F=256)
    uint32_t* wh   = (uint32_t*)whp;
    uint32_t* wl   = (uint32_t*)wlp;

    // pre-conversions (conv_x also zeros counters)
    conv_x_kernel<<<(N_NODES * F_IN / 4 + 255) / 256, 256>>>(x);
    conv_wp_kernel<<<(32768 + 255) / 256, 256>>>(W1, wh + W1P_OFF, wl + W1P_OFF, F_IN, H1);
    conv_wp_kernel<<<(65536 + 255) / 256, 256>>>(W2, wh + W2P_OFF, wl + W2P_OFF, H1, H2);
    conv_wp_kernel<<<(16384 + 255) / 256, 256>>>(W3, wh + W3P_OFF, wl + W3P_OFF, H2, H3);

    // CSR build (by target) + dinv
    count_deg_kernel<<<(N_EDGES + 255) / 256, 256>>>(ei);
    partial_sum_kernel<<<SCAN_NB, 1024>>>();
    scan_bsum_kernel<<<1, 64>>>();
    offsets_kernel<<<SCAN_NB, 1024>>>();
    fill_csr_kernel<<<(N_EDGES + 255) / 256, 256>>>(ei);

    const int MB = (N_NODES + 127) / 128;   // 391

    // layer 1: aggX = A_hat x -> scr ; h1 = aggX @ W1 -> b16a (fused exact stats)
    gather_bf16_kernel<false><<<dim3(N_NODES / 8, 1), 256>>>(b16b, scr, F_IN);
    gemm_bf16_kernel<false, true><<<dim3(H1 / 128, MB), 256>>>(
        scr, wh + W1P_OFF, wl + W1P_OFF, b16a, N_NODES, F_IN, H1);
    bn_finalize_kernel<false><<<1, H1>>>(g1, be1);

    // layer 2: h2 = relu(bn(h1)) @ W2 -> b16b ; agg2 = A_hat h2 -> scr (+stats)
    gemm_bf16_kernel<true, false><<<dim3(H2 / 128, MB), 256>>>(
        b16a, wh + W2P_OFF, wl + W2P_OFF, b16b, N_NODES, H1, H2);
    gather_bf16_kernel<true><<<dim3(N_NODES / 8, H2 / 128), 256>>>(b16b, scr, H2);
    bn_finalize_kernel<false><<<1, H2>>>(g2, be2);

    // layer 3: h3 = relu(bn(agg2)) @ W3 -> b16a ; agg3 = A_hat h3 -> g_h3 (+stats)
    gemm_bf16_kernel<true, false><<<dim3(H3 / 128, MB), 256>>>(
        scr, wh + W3P_OFF, wl + W3P_OFF, b16a, N_NODES, H2, H3);
    gather_bf16_kernel<true><<<dim3(N_NODES / 8, 1), 256>>>(b16a, h3b, H3);
    bn_finalize_kernel<true><<<1, H3>>>(g3, be3);   // also zeros pool

    // pool (BN3+ReLU fused) + output head
    pool_kernel<<<(N_NODES + 31) / 32, 128>>>(batch);
    final_linear_kernel<<<(N_GRAPHS * N_CLS + 255) / 256, 256>>>(Wo, bo, out);
}